// round 13
// baseline (speedup 1.0000x reference)
#include <cuda_runtime.h>
#include <cuda_bf16.h>
#include <math.h>

#define PI_F 3.14159265358979323846f

#define BATCH 128
#define NF2 40

// ---------------- device tables ----------------
__device__ float  g_w2n[12];

__device__ float2 g_T60[10 * 60];        // e^{-2pi i m a/60}, m=0..9
__device__ float2 g_E20P[19 * 20];       // e^{+2pi i (ni-9) x/20}
__device__ float2 g_E20M[11 * 20];       // e^{-2pi i (mi-5) x/20}
__device__ float2 g_E12P[11 * 12];       // e^{+2pi i (ni-5) x/12}

__device__ float  g_wd_s2[10 * 60 * 10];     // [l][b][m]
__device__ float  g_d1w[10 * 20 * 10 * 19];  // [l][b][m][ni]
__device__ float  g_d12w[6 * 20 * 6 * 11];   // [l][b][m][ki]
__device__ float  g_d2w[6 * 12 * 6 * 11];    // [l][b][m][ni]
__device__ float2 g_Y1[10 * 24 * 19];        // [l][g][ni]
__device__ float2 g_D2[6 * 144 * 11 * 11];   // [l][g][ki][ni]

__device__ __align__(16) float2 g_E1[20 * 20 * 2000]; // [o][b][(m*20+g)*10+l]
__device__ __align__(16) float2 g_X[BATCH * 100];     // [z][m*10+l]
__device__ __align__(16) float2 g_Yg[(size_t)BATCH * 20 * 20 * 66]; // [z][c][b][m*11+ni]
__device__ __align__(16) float2 g_Fx[(size_t)128 * 3220]; // packed [p][z][ik]
__device__ __align__(16) float2 g_B2[316800];         // packed [l][ik][o*11+ni]
__device__ float2 g_Fo[(size_t)BATCH * NF2 * 21 * 11];// [z][o][p][ni]
__device__ float  g_feat[BATCH * NF2];

// p = (l,m) valid pairs, m<=l<=5
__constant__ int cPl[21]   = {0,1,1,2,2,2,3,3,3,3,4,4,4,4,4,5,5,5,5,5,5};
__constant__ int cPref[21] = {0,20,80,140,240,340,440,580,720,860,1000,1180,1360,1540,1720,1900,2120,2340,2560,2780,3000};
__constant__ int cOutOff[22] = {0,1,4,7,12,17,22,29,36,43,50,59,68,77,86,95,106,117,128,139,150,161};
__constant__ int cPm[21]   = {0,0,1,0,1,2,0,1,2,3,0,1,2,3,4,0,1,2,3,4,5};
__constant__ int cBl[36]  = {0,1,1,1,2,2,2,2,2,3,3,3,3,3,3,3,4,4,4,4,4,4,4,4,4,5,5,5,5,5,5,5,5,5,5,5};
__constant__ int cBkk[36] = {0,0,1,2,0,1,2,3,4,0,1,2,3,4,5,6,0,1,2,3,4,5,6,7,8,0,1,2,3,4,5,6,7,8,9,10};
// t -> (p, kk) lookup for k_Fx (t = cOutOff[p] + kk)
__constant__ signed char cT2P[161] = {
0,
1,1,1,
2,2,2,
3,3,3,3,3,
4,4,4,4,4,
5,5,5,5,5,
6,6,6,6,6,6,6,
7,7,7,7,7,7,7,
8,8,8,8,8,8,8,
9,9,9,9,9,9,9,
10,10,10,10,10,10,10,10,10,
11,11,11,11,11,11,11,11,11,
12,12,12,12,12,12,12,12,12,
13,13,13,13,13,13,13,13,13,
14,14,14,14,14,14,14,14,14,
15,15,15,15,15,15,15,15,15,15,15,
16,16,16,16,16,16,16,16,16,16,16,
17,17,17,17,17,17,17,17,17,17,17,
18,18,18,18,18,18,18,18,18,18,18,
19,19,19,19,19,19,19,19,19,19,19,
20,20,20,20,20,20,20,20,20,20,20};
__constant__ signed char cT2KK[161] = {
0,
0,1,2,
0,1,2,
0,1,2,3,4,
0,1,2,3,4,
0,1,2,3,4,
0,1,2,3,4,5,6,
0,1,2,3,4,5,6,
0,1,2,3,4,5,6,
0,1,2,3,4,5,6,
0,1,2,3,4,5,6,7,8,
0,1,2,3,4,5,6,7,8,
0,1,2,3,4,5,6,7,8,
0,1,2,3,4,5,6,7,8,
0,1,2,3,4,5,6,7,8,
0,1,2,3,4,5,6,7,8,9,10,
0,1,2,3,4,5,6,7,8,9,10,
0,1,2,3,4,5,6,7,8,9,10,
0,1,2,3,4,5,6,7,8,9,10,
0,1,2,3,4,5,6,7,8,9,10,
0,1,2,3,4,5,6,7,8,9,10};

__device__ __forceinline__ float fpow_i(float x, int p) {
    float r = 1.f;
    for (int i = 0; i < p; ++i) r *= x;
    return r;
}

__device__ float wigf(const float* lf, int l, int m, int n, float beta) {
    if (m > l || m < -l || n > l || n < -l) return 0.f;
    float cb = cosf(0.5f * beta), sb = sinf(0.5f * beta);
    float pref = 0.5f * (lf[l + m] + lf[l - m] + lf[l + n] + lf[l - n]);
    int s0 = max(0, n - m), s1 = min(l + n, l - m);
    float acc = 0.f;
    for (int s = s0; s <= s1; ++s) {
        float c = pref - (lf[l + n - s] + lf[s] + lf[m - n + s] + lf[l - m - s]);
        float t = expf(c) * fpow_i(cb, 2 * l + n - m - 2 * s) * fpow_i(sb, m - n + 2 * s);
        acc += ((m - n + s) & 1) ? -t : t;
    }
    return acc;
}

__device__ float dh_w_f(int bsz, int k) {
    float beta = PI_F * (2 * k + 1) / (4.0f * bsz);
    float s = 0.0f;
    for (int j = 0; j < bsz; ++j)
        s += sinf((2 * j + 1) * beta) / (2 * j + 1);
    return (2.0f / bsz) * sinf(beta) * s;
}

// ---------------- merged setup (all fp32) ----------------
#define O_D1W  6000
#define O_D12W 44000
#define O_D2W  51920
#define O_Y1s  56672
#define O_D2s  61232
#define N_SET2 165776
#define SET_TAB_BASE 2048

__global__ void k_setup() {
    __shared__ float s_lf[64];
    int tid = threadIdx.x;
    if (tid < 64) s_lf[tid] = lgammaf(tid + 1.0f);
    __syncthreads();
    int idx = blockIdx.x * blockDim.x + tid;
    if (idx < 1344) {
        if (idx < 600) {
            int m = idx / 60, a = idx % 60;
            float th = -2.0f * PI_F * m * a / 60.0f;
            float sn, cs; sincosf(th, &sn, &cs);
            g_T60[idx] = make_float2(cs, sn);
        } else if (idx < 980) {
            int r = idx - 600; int ni = r / 20, x = r % 20;
            float th = 2.0f * PI_F * (ni - 9) * x / 20.0f;
            float sn, cs; sincosf(th, &sn, &cs);
            g_E20P[r] = make_float2(cs, sn);
        } else if (idx < 1200) {
            int r = idx - 980; int mi = r / 20, x = r % 20;
            float th = -2.0f * PI_F * (mi - 5) * x / 20.0f;
            float sn, cs; sincosf(th, &sn, &cs);
            g_E20M[r] = make_float2(cs, sn);
        } else if (idx < 1332) {
            int r = idx - 1200; int ni = r / 12, x = r % 12;
            float th = 2.0f * PI_F * (ni - 5) * x / 12.0f;
            float sn, cs; sincosf(th, &sn, &cs);
            g_E12P[r] = make_float2(cs, sn);
        } else {
            int k = idx - 1332;
            float s = 0.0f;
            for (int j = 0; j < 12; ++j) s += dh_w_f(6, j);
            g_w2n[k] = dh_w_f(6, k) / s;
        }
        return;
    }
    if (idx < SET_TAB_BASE) return;
    int i2 = idx - SET_TAB_BASE;
    if (i2 >= N_SET2) return;
    if (i2 < O_D1W) {
        int i = i2;
        int l = i / 600, b = (i % 600) / 10, m = i % 10;
        float beta = PI_F * (2 * b + 1) / 120.0f;
        g_wd_s2[i] = dh_w_f(30, b) * wigf(s_lf, l, m, 0, beta);
    } else if (i2 < O_D12W) {
        int i = i2 - O_D1W;
        int l = i / 3800; int r = i % 3800;
        int b = r / 190; int q = r % 190;
        int m = q / 19, ni = q % 19;
        float beta = PI_F * (2 * b + 1) / 40.0f;
        g_d1w[i] = (2 * l + 1) * wigf(s_lf, l, m, ni - 9, beta);
    } else if (i2 < O_D2W) {
        int i = i2 - O_D12W;
        int l = i / 1320; int r = i % 1320;
        int b = r / 66; int q = r % 66;
        int m = q / 11, ki = q % 11;
        float beta = PI_F * (2 * b + 1) / 40.0f;
        g_d12w[i] = dh_w_f(10, b) * wigf(s_lf, l, m, ki - 5, beta);
    } else if (i2 < O_Y1s) {
        int i = i2 - O_D2W;
        int l = i / 792; int r = i % 792;
        int b = r / 66; int q = r % 66;
        int m = q / 11, ni = q % 11;
        float beta = PI_F * (2 * b + 1) / 24.0f;
        g_d2w[i] = (2 * l + 1) * wigf(s_lf, l, m, ni - 5, beta);
    } else if (i2 < O_D2s) {
        int i = i2 - O_Y1s;
        int l = i / (24 * 19); int r = i % (24 * 19);
        int g = r / 19, mi = r % 19;
        int ib = g / 8, ja = g % 8;
        float beta = (ib + 1) * PI_F / 24.0f;
        float alpha = 2.0f * PI_F * ja / 8.0f;
        int m = mi - 9;
        float d = wigf(s_lf, l, m, 0, beta);
        float th = -(float)m * alpha;
        float sn, cs; sincosf(th, &sn, &cs);
        g_Y1[i] = make_float2(d * cs, d * sn);
    } else {
        int i = i2 - O_D2s;
        int l = i / (144 * 121); int r = i % (144 * 121);
        int g = r / 121; int q = r % 121;
        int ki = q / 11, ni = q % 11;
        int ib = g / 48, ja = (g / 6) % 8, kg = g % 6;
        float beta = (ib + 1) * PI_F / 24.0f;
        float alpha = 2.0f * PI_F * ja / 8.0f;
        float gamma = 2.0f * PI_F * kg / 6.0f;
        int m = ki - 5, n = ni - 5;
        float d = wigf(s_lf, l, m, n, beta);
        float th = -((float)m * alpha + (float)n * gamma);
        float sn, cs; sincosf(th, &sn, &cs);
        g_D2[i] = make_float2(d * cs, d * sn);
    }
}

// ---------------- merged prep: E1 (0..399), B2 (400..1839), X (1840..1967) ----------------
#define PREP_E1_N 400
#define PREP_B2_N 1440
#define PREP_X_BASE (PREP_E1_N + PREP_B2_N)
#define PREP_TOTAL (PREP_X_BASE + BATCH)

__global__ __launch_bounds__(256) void k_prep(const float* __restrict__ psi1,
                                              const float* __restrict__ psi2,
                                              const float* __restrict__ x) {
    __shared__ __align__(16) char sbuf[24576];
    int blk = blockIdx.x;
    int tid = threadIdx.x;

    if (blk < PREP_E1_N) {
        int b = blk % 20, o = blk / 20;
        float2* sPsi  = (float2*)sbuf;                 // 190
        float*  sd1w  = (float*)(sbuf + 1520);         // 1900
        float2* sE20P = (float2*)(sbuf + 9120);        // 380
        for (int t = tid; t < 190; t += 256) {
            int l = t / 19, ni = t % 19;
            float2 acc = make_float2(0.f, 0.f);
            for (int g = 0; g < 24; ++g) {
                float w = psi1[o * 24 + g];
                float2 y = g_Y1[(l * 24 + g) * 19 + ni];
                acc.x += w * y.x; acc.y += w * y.y;
            }
            sPsi[t] = acc;
        }
        for (int t = tid; t < 1900; t += 256) {
            int l = t / 190, m = (t / 19) % 10, ni = t % 19;
            sd1w[t] = g_d1w[((l * 20 + b) * 10 + m) * 19 + ni];
        }
        for (int t = tid; t < 380; t += 256) sE20P[t] = g_E20P[t];
        __syncthreads();
        for (int t = tid; t < 2000; t += 256) {
            int l = t % 10;
            int g = (t / 10) % 20;
            int m = t / 200;
            float2 acc = make_float2(0.f, 0.f);
            const float* dw = &sd1w[(l * 10 + m) * 19];
            const float2* ps = &sPsi[l * 19];
            for (int ni = 0; ni < 19; ++ni) {
                float d = dw[ni];
                float2 p = ps[ni];
                float2 e = sE20P[ni * 20 + g];
                acc.x += d * (p.x * e.x - p.y * e.y);
                acc.y += d * (p.x * e.y + p.y * e.x);
            }
            g_E1[(size_t)(o * 20 + b) * 2000 + t] = acc;
        }
    } else if (blk < PREP_X_BASE) {
        int q = blk - PREP_E1_N;
        int s = q / 40, rg = q % 40;
        int l = cBl[s], kk = cBkk[s];
        int kidx = kk - l + 5;
        float2* sD = (float2*)sbuf;                    // 1584
        float*  sP = (float*)(sbuf + 12672);           // 20*145
        for (int t = tid; t < 1584; t += 256) {
            int g = t / 11, ni = t % 11;
            sD[t] = g_D2[((l * 144 + g) * 11 + kidx) * 11 + ni];
        }
        int row0 = rg * 20;
        for (int t = tid; t < 20 * 144; t += 256) {
            int r = t / 144, g = t % 144;
            sP[r * 145 + g] = psi2[(size_t)(row0 + r) * 144 + g];
        }
        __syncthreads();
        if (tid < 220) {
            int rl = tid / 11, ni = tid % 11;
            int pr = row0 + rl;
            float2 acc = make_float2(0.f, 0.f);
            const float* pp = &sP[rl * 145];
            #pragma unroll 8
            for (int g = 0; g < 144; ++g) {
                float w = pp[g];
                float2 d = sD[g * 11 + ni];
                acc.x += w * d.x; acc.y += w * d.y;
            }
            int i = pr / 40, o = pr % 40;
            g_B2[(size_t)8800 * l * l + (size_t)(i * (2 * l + 1) + kk) * 440 + o * 11 + ni] = acc;
        }
    } else {
        int z = blk - PREP_X_BASE;
        float*  sx  = (float*)sbuf;                    // 3600
        float2* sxf = (float2*)(sbuf + 14400);         // 600
        for (int t = tid; t < 3600; t += 256)
            sx[t] = x[(size_t)z * 3600 + t];
        __syncthreads();
        for (int t = tid; t < 600; t += 256) {
            int b = t / 10, m = t % 10;
            float re = 0.f, im = 0.f;
            const float* row = &sx[b * 60];
            const float2* tw = &g_T60[m * 60];
            for (int a = 0; a < 60; ++a) {
                float v = row[a];
                re += v * tw[a].x; im += v * tw[a].y;
            }
            sxf[t] = make_float2(re, im);
        }
        __syncthreads();
        for (int t = tid; t < 100; t += 256) {
            int l = t / 10, m = t % 10;
            float2 acc = make_float2(0.f, 0.f);
            for (int b = 0; b < 60; ++b) {
                float w = g_wd_s2[(l * 60 + b) * 10 + m];
                float2 v = sxf[b * 10 + m];
                acc.x += w * v.x; acc.y += w * v.y;
            }
            g_X[z * 100 + m * 10 + l] = acc;
        }
    }
}

// ---------------- fused mid (radix-2, in-place A butterfly) — R10 version ----------------
__global__ __launch_bounds__(320) void k_mid() {
    __shared__ __align__(16) float2 sE1[2000]; // [m][g][l]
    __shared__ float2 sTw1[200];               // [m][a], x2 m>=1
    __shared__ float2 sEm[220];                // [mi][x]
    __shared__ __align__(16) float2 sX[1600];  // [zz][m*10+l]
    __shared__ float2 sA[1920];                // [zz][m2*20+g]
    int b = blockIdx.x, c = blockIdx.y;
    int tid = threadIdx.x;
    const float2* e1 = g_E1 + (size_t)(c * 20 + b) * 2000;
    for (int t = tid; t < 2000; t += 320) sE1[t] = e1[t];
    for (int t = tid; t < 200; t += 320) {
        int m = t / 20;
        float2 e = g_E20P[(m + 9) * 20 + t % 20];
        float s = (m >= 1) ? 2.f : 1.f;
        sTw1[t] = make_float2(s * e.x, s * e.y);
    }
    for (int t = tid; t < 220; t += 320) sEm[t] = g_E20M[t];
    __syncthreads();
    int zz = tid / 20, g = tid % 20;
    for (int stage = 0; stage < 8; ++stage) {
        int z0 = stage * 16;
        for (int t = tid; t < 1600; t += 320)
            sX[t] = g_X[(z0 + t / 100) * 100 + t % 100];
        __syncthreads();
        float2 S1m[10];
        #pragma unroll
        for (int m = 0; m < 10; ++m) {
            const float4* xp = (const float4*)&sX[zz * 100 + m * 10];
            const float4* ep = (const float4*)&sE1[(m * 20 + g) * 10];
            float ar = 0.f, ai = 0.f;
            #pragma unroll
            for (int i = 0; i < 5; ++i) {
                float4 xv = xp[i];
                float4 ev = ep[i];
                ar += xv.x * ev.x - xv.y * ev.y;
                ai += xv.x * ev.y + xv.y * ev.x;
                ar += xv.z * ev.z - xv.w * ev.w;
                ai += xv.z * ev.w + xv.w * ev.z;
            }
            S1m[m] = make_float2(ar, ai);
        }
        float ys[10], yd[10];
        #pragma unroll
        for (int a = 0; a < 10; ++a) {
            float ve = S1m[0].x, vo = 0.f;
            #pragma unroll
            for (int m = 1; m < 10; ++m) {
                float2 e = sTw1[m * 20 + a];
                float tt = S1m[m].x * e.x - S1m[m].y * e.y;
                if (m & 1) vo += tt; else ve += tt;
            }
            float y0 = fmaxf(ve + vo, 0.f);
            float y1 = fmaxf(ve - vo, 0.f);
            ys[a] = y0 + y1;
            yd[a] = y0 - y1;
        }
        #pragma unroll
        for (int m2 = 0; m2 < 6; ++m2) {
            const float2* ep = &sEm[(m2 + 5) * 20];
            const float* yy = (m2 & 1) ? yd : ys;
            float ar = 0.f, ai = 0.f;
            #pragma unroll
            for (int a = 0; a < 10; ++a) {
                ar += yy[a] * ep[a].x;
                ai += yy[a] * ep[a].y;
            }
            sA[zz * 120 + m2 * 20 + g] = make_float2(ar, ai);
        }
        __syncthreads();
        for (int t = tid; t < 960; t += 320) {
            int zz2 = t / 60, m2 = (t / 10) % 6, a = t % 10;
            int base = zz2 * 120 + m2 * 20;
            float2 p = sA[base + a];
            float2 q = sA[base + a + 10];
            sA[base + a]      = make_float2(p.x + q.x, p.y + q.y);
            sA[base + a + 10] = make_float2(p.x - q.x, p.y - q.y);
        }
        __syncthreads();
        for (int t = tid; t < 1056; t += 320) {
            int zz2 = t / 66, r = t % 66;
            int m = r / 11, ni = r % 11;
            int odd = (ni - 5) & 1;
            const float2* ap = &sA[zz2 * 120 + m * 20 + odd * 10];
            const float2* ep = &sEm[ni * 20];
            float2 acc = make_float2(0.f, 0.f);
            #pragma unroll
            for (int gg = 0; gg < 10; ++gg) {
                float2 av = ap[gg], e = ep[gg];
                acc.x += av.x * e.x - av.y * e.y;
                acc.y += av.x * e.y + av.y * e.x;
            }
            int z = z0 + zz2;
            g_Yg[((size_t)((z * 20 + c) * 20 + b)) * 66 + r] = acc;
        }
        __syncthreads();
    }
}

// ---------------- Fx packed: 2 zi per block, d12w reuse, float4 Yg loads ----------------
__global__ __launch_bounds__(256) void k_Fx() {
    __shared__ __align__(16) float2 sYs[2 * 1320]; // [pair][b][m*11+ni]
    int zi0 = blockIdx.x * 2;
    const float4* src = (const float4*)(g_Yg + (size_t)zi0 * 1320);
    float4* dst = (float4*)sYs;
    for (int t = threadIdx.x; t < 1320; t += 256)
        dst[t] = src[t];
    __syncthreads();
    int t = threadIdx.x;
    if (t < 161) {
        int p = cT2P[t];
        int kk = cT2KK[t];
        int l = cPl[p], m = cPm[p];
        int kidx = kk - l + 5;
        int off = m * 11 + kidx;
        float2 acc0 = make_float2(0.f, 0.f);
        float2 acc1 = make_float2(0.f, 0.f);
        const float* dwp = &g_d12w[(l * 20 * 6 + m) * 11 + kidx];
        const float2* y0 = &sYs[off];
        const float2* y1 = &sYs[1320 + off];
        #pragma unroll
        for (int b = 0; b < 20; ++b) {
            float d = dwp[b * 66];
            float2 v0 = y0[b * 66];
            float2 v1 = y1[b * 66];
            acc0.x += d * v0.x; acc0.y += d * v0.y;
            acc1.x += d * v1.x; acc1.y += d * v1.y;
        }
        int Kl = 20 * (2 * l + 1);
        int z = zi0 / 20, i = zi0 % 20;
        int z1 = (zi0 + 1) / 20, i1 = (zi0 + 1) % 20;
        g_Fx[(size_t)cPref[p] * 128 + (size_t)z * Kl + i * (2 * l + 1) + kk] = acc0;
        g_Fx[(size_t)cPref[p] * 128 + (size_t)z1 * Kl + i1 * (2 * l + 1) + kk] = acc1;
    }
}

// ---------------- Fo GEMM (heavy-l first, ik-paired float4, FO_ZT=4) ----------------
#define FO_ZT 4
__global__ void k_Fo() {
    __shared__ __align__(16) float2 sAa[FO_ZT * 220];
    int p = 20 - blockIdx.x;
    int z0 = blockIdx.y * FO_ZT;
    int l = cPl[p];
    int Kl = 20 * (2 * l + 1);
    size_t abase = (size_t)cPref[p] * 128 + (size_t)z0 * Kl;
    for (int t = threadIdx.x; t < FO_ZT * Kl; t += blockDim.x)
        sAa[t] = g_Fx[abase + t];
    __syncthreads();
    int t = threadIdx.x;
    if (t < 220) {
        float2 a0[FO_ZT], a1[FO_ZT];
        #pragma unroll
        for (int zz = 0; zz < FO_ZT; ++zz) { a0[zz] = make_float2(0.f, 0.f); a1[zz] = make_float2(0.f, 0.f); }
        const float4* Bp = (const float4*)(g_B2 + (size_t)8800 * l * l);
        const float4* Ap = (const float4*)sAa;
        for (int ik = 0; ik < Kl; ik += 2) {
            float4 b0 = Bp[ik * 220 + t];
            float4 b1 = Bp[(ik + 1) * 220 + t];
            #pragma unroll
            for (int zz = 0; zz < FO_ZT; ++zz) {
                float4 av = Ap[(zz * Kl + ik) >> 1]; // (re0,im0,re1,im1)
                a0[zz].x += av.x * b0.x - av.y * b0.y;
                a0[zz].y += av.x * b0.y + av.y * b0.x;
                a1[zz].x += av.x * b0.z - av.y * b0.w;
                a1[zz].y += av.x * b0.w + av.y * b0.z;
                a0[zz].x += av.z * b1.x - av.w * b1.y;
                a0[zz].y += av.z * b1.y + av.w * b1.x;
                a1[zz].x += av.z * b1.z - av.w * b1.w;
                a1[zz].y += av.z * b1.w + av.w * b1.z;
            }
        }
        int o0 = (2 * t) / 11, n0 = (2 * t) % 11;
        int o1 = (2 * t + 1) / 11, n1 = (2 * t + 1) % 11;
        #pragma unroll
        for (int zz = 0; zz < FO_ZT; ++zz) {
            int z = z0 + zz;
            g_Fo[((size_t)(z * 40 + o0) * 21 + p) * 11 + n0] = a0[zz];
            g_Fo[((size_t)(z * 40 + o1) * 21 + p) * 11 + n1] = a1[zz];
        }
    }
}

// ---------------- final: 2 zo per block (radix-2 on both 12-pt stages) ----------------
__global__ __launch_bounds__(128) void k_final() {
    __shared__ float2 sFo[462];    // [h][p*11+ni]
    __shared__ float2 sE12[132];
    __shared__ float2 sFh2[1584];  // [h][(b*6+m)*11+ni]
    __shared__ float2 sU[1728];    // [h][(b*6+m)*12+g]
    __shared__ float  sw2[12];
    __shared__ float  sred[256];
    int zo0 = blockIdx.x * 2;
    int tid = threadIdx.x;
    for (int t = tid; t < 462; t += 128) sFo[t] = g_Fo[(size_t)zo0 * 231 + t];
    for (int t = tid; t < 132; t += 128) sE12[t] = g_E12P[t];
    if (tid < 12) sw2[tid] = g_w2n[tid];
    __syncthreads();
    for (int t = tid; t < 1584; t += 128) {
        int h = t / 792;
        int r2 = t % 792;
        int b = r2 / 66, r = r2 % 66;
        int m = r / 11, ni = r % 11;
        float2 acc = make_float2(0.f, 0.f);
        for (int l = m; l < 6; ++l) {
            float d = g_d2w[((l * 12 + b) * 6 + m) * 11 + ni];
            float2 f = sFo[h * 231 + (l * (l + 1) / 2 + m) * 11 + ni];
            acc.x += d * f.x; acc.y += d * f.y;
        }
        sFh2[t] = acc;
    }
    __syncthreads();
    for (int t = tid; t < 864; t += 128) {
        int h = t / 432;
        int r2 = t % 432;
        int bm = r2 / 6, g = r2 % 6;
        float2 ue = make_float2(0.f, 0.f), uo = make_float2(0.f, 0.f);
        const float2* fp = &sFh2[h * 792 + bm * 11];
        #pragma unroll
        for (int ni = 0; ni < 11; ++ni) {
            float2 f = fp[ni];
            float2 e = sE12[ni * 12 + g];
            float tr = f.x * e.x - f.y * e.y;
            float ti = f.x * e.y + f.y * e.x;
            if ((ni - 5) & 1) { uo.x += tr; uo.y += ti; }
            else              { ue.x += tr; ue.y += ti; }
        }
        sU[h * 864 + bm * 12 + g]     = make_float2(ue.x + uo.x, ue.y + uo.y);
        sU[h * 864 + bm * 12 + g + 6] = make_float2(ue.x - uo.x, ue.y - uo.y);
    }
    __syncthreads();
    float part0 = 0.f, part1 = 0.f;
    for (int t = tid; t < 1728; t += 128) {
        int h = t / 864;
        int r2 = t % 864;
        int bq = r2 / 72, r = r2 % 72;
        int a = r / 12, g = r % 12;
        const float2* up = &sU[h * 864 + bq * 72 + g];
        float ve = up[0].x, vo = 0.f;
        #pragma unroll
        for (int m = 1; m < 6; ++m) {
            float2 u = up[m * 12];
            float2 e = sE12[(m + 5) * 12 + a];
            float tt = 2.f * (u.x * e.x - u.y * e.y);
            if (m & 1) vo += tt; else ve += tt;
        }
        float v0 = ve + vo, v1 = ve - vo;
        float s = 0.f;
        if (v0 > 0.f) s += v0;
        if (v1 > 0.f) s += v1;
        if (h) part1 += sw2[bq] * s; else part0 += sw2[bq] * s;
    }
    sred[tid] = part0;
    sred[128 + tid] = part1;
    __syncthreads();
    for (int s = 64; s > 0; s >>= 1) {
        if (tid < s) {
            sred[tid] += sred[tid + s];
            sred[128 + tid] += sred[128 + tid + s];
        }
        __syncthreads();
    }
    if (tid == 0) {
        g_feat[zo0]     = sred[0]   * (1.0f / 144.0f);
        g_feat[zo0 + 1] = sred[128] * (1.0f / 144.0f);
    }
}

// ---------------- linear head ----------------
__global__ void k_lin(const float* __restrict__ w_lin, const float* __restrict__ b_lin,
                      float* __restrict__ out) {
    int t = blockIdx.x * blockDim.x + threadIdx.x;
    if (t >= BATCH * 10) return;
    int z = t / 10, f = t % 10;
    float acc = b_lin[f];
    #pragma unroll
    for (int o = 0; o < NF2; ++o)
        acc += g_feat[z * NF2 + o] * w_lin[f * NF2 + o];
    out[t] = acc;
}

// ---------------- launch ----------------
extern "C" void kernel_launch(void* const* d_in, const int* in_sizes, int n_in,
                              void* d_out, int out_size) {
    const float* x     = (const float*)d_in[0];
    const float* psi1  = (const float*)d_in[1];
    const float* psi2  = (const float*)d_in[2];
    const float* w_lin = (const float*)d_in[3];
    const float* b_lin = (const float*)d_in[4];
    float* out = (float*)d_out;

    k_setup<<<(SET_TAB_BASE + N_SET2 + 255) / 256, 256>>>();
    k_prep<<<PREP_TOTAL, 256>>>(psi1, psi2, x);
    k_mid<<<dim3(20, 20), 320>>>();
    k_Fx<<<BATCH * 20 / 2, 256>>>();
    k_Fo<<<dim3(21, BATCH / FO_ZT), 256>>>();
    k_final<<<BATCH * NF2 / 2, 128>>>();
    k_lin<<<(BATCH * 10 + 255) / 256, 256>>>(w_lin, b_lin, out);
}

// round 14
// speedup vs baseline: 1.0128x; 1.0128x over previous
#include <cuda_runtime.h>
#include <cuda_bf16.h>
#include <math.h>

#define PI_F 3.14159265358979323846f

#define BATCH 128
#define NF2 40

// ---------------- device tables ----------------
__device__ float  g_w2n[12];

__device__ float2 g_T60[10 * 60];        // e^{-2pi i m a/60}, m=0..9
__device__ float2 g_E20P[19 * 20];       // e^{+2pi i (ni-9) x/20}
__device__ float2 g_E20M[11 * 20];       // e^{-2pi i (mi-5) x/20}
__device__ float2 g_E12P[11 * 12];       // e^{+2pi i (ni-5) x/12}

__device__ float  g_wd_s2[10 * 60 * 10];     // [l][b][m]
__device__ float  g_d1w[10 * 20 * 10 * 19];  // [l][b][m][ni]
__device__ float  g_d12w[6 * 20 * 6 * 11];   // [l][b][m][ki]
__device__ float  g_d2w[6 * 12 * 6 * 11];    // [l][b][m][ni]
__device__ float2 g_Y1[10 * 24 * 19];        // [l][g][ni]
__device__ float2 g_D2[6 * 144 * 11 * 11];   // [l][g][ki][ni]

__device__ __align__(16) float2 g_E1[20 * 20 * 2000]; // [o][b][(m*20+g)*10+l]
__device__ __align__(16) float2 g_X[BATCH * 100];     // [z][m*10+l]
__device__ __align__(16) float2 g_Yg[(size_t)BATCH * 20 * 20 * 66]; // [z][c][b][m*11+ni]
__device__ __align__(16) float2 g_Fx[(size_t)128 * 3220]; // packed [p][z][ik]
__device__ __align__(16) float2 g_B2[316800];         // packed [l][ik][o*11+ni]
__device__ float2 g_Fo[(size_t)BATCH * NF2 * 21 * 11];// [z][o][p][ni]
__device__ float  g_feat[BATCH * NF2];

// p = (l,m) valid pairs, m<=l<=5
__constant__ int cPl[21]   = {0,1,1,2,2,2,3,3,3,3,4,4,4,4,4,5,5,5,5,5,5};
__constant__ int cPref[21] = {0,20,80,140,240,340,440,580,720,860,1000,1180,1360,1540,1720,1900,2120,2340,2560,2780,3000};
__constant__ int cOutOff[22] = {0,1,4,7,12,17,22,29,36,43,50,59,68,77,86,95,106,117,128,139,150,161};
__constant__ int cPm[21]   = {0,0,1,0,1,2,0,1,2,3,0,1,2,3,4,0,1,2,3,4,5};
__constant__ int cBl[36]  = {0,1,1,1,2,2,2,2,2,3,3,3,3,3,3,3,4,4,4,4,4,4,4,4,4,5,5,5,5,5,5,5,5,5,5,5};
__constant__ int cBkk[36] = {0,0,1,2,0,1,2,3,4,0,1,2,3,4,5,6,0,1,2,3,4,5,6,7,8,0,1,2,3,4,5,6,7,8,9,10};
// t -> (p, kk) lookup for k_Fx (t = cOutOff[p] + kk)
__constant__ signed char cT2P[161] = {
0,
1,1,1,
2,2,2,
3,3,3,3,3,
4,4,4,4,4,
5,5,5,5,5,
6,6,6,6,6,6,6,
7,7,7,7,7,7,7,
8,8,8,8,8,8,8,
9,9,9,9,9,9,9,
10,10,10,10,10,10,10,10,10,
11,11,11,11,11,11,11,11,11,
12,12,12,12,12,12,12,12,12,
13,13,13,13,13,13,13,13,13,
14,14,14,14,14,14,14,14,14,
15,15,15,15,15,15,15,15,15,15,15,
16,16,16,16,16,16,16,16,16,16,16,
17,17,17,17,17,17,17,17,17,17,17,
18,18,18,18,18,18,18,18,18,18,18,
19,19,19,19,19,19,19,19,19,19,19,
20,20,20,20,20,20,20,20,20,20,20};
__constant__ signed char cT2KK[161] = {
0,
0,1,2,
0,1,2,
0,1,2,3,4,
0,1,2,3,4,
0,1,2,3,4,
0,1,2,3,4,5,6,
0,1,2,3,4,5,6,
0,1,2,3,4,5,6,
0,1,2,3,4,5,6,
0,1,2,3,4,5,6,7,8,
0,1,2,3,4,5,6,7,8,
0,1,2,3,4,5,6,7,8,
0,1,2,3,4,5,6,7,8,
0,1,2,3,4,5,6,7,8,
0,1,2,3,4,5,6,7,8,9,10,
0,1,2,3,4,5,6,7,8,9,10,
0,1,2,3,4,5,6,7,8,9,10,
0,1,2,3,4,5,6,7,8,9,10,
0,1,2,3,4,5,6,7,8,9,10,
0,1,2,3,4,5,6,7,8,9,10};

__device__ __forceinline__ float fpow_i(float x, int p) {
    float r = 1.f;
    for (int i = 0; i < p; ++i) r *= x;
    return r;
}

__device__ float wigf(const float* lf, int l, int m, int n, float beta) {
    if (m > l || m < -l || n > l || n < -l) return 0.f;
    float cb = cosf(0.5f * beta), sb = sinf(0.5f * beta);
    float pref = 0.5f * (lf[l + m] + lf[l - m] + lf[l + n] + lf[l - n]);
    int s0 = max(0, n - m), s1 = min(l + n, l - m);
    float acc = 0.f;
    for (int s = s0; s <= s1; ++s) {
        float c = pref - (lf[l + n - s] + lf[s] + lf[m - n + s] + lf[l - m - s]);
        float t = expf(c) * fpow_i(cb, 2 * l + n - m - 2 * s) * fpow_i(sb, m - n + 2 * s);
        acc += ((m - n + s) & 1) ? -t : t;
    }
    return acc;
}

__device__ float dh_w_f(int bsz, int k) {
    float beta = PI_F * (2 * k + 1) / (4.0f * bsz);
    float s = 0.0f;
    for (int j = 0; j < bsz; ++j)
        s += sinf((2 * j + 1) * beta) / (2 * j + 1);
    return (2.0f / bsz) * sinf(beta) * s;
}

// ---------------- merged setup (all fp32) ----------------
#define O_D1W  6000
#define O_D12W 44000
#define O_D2W  51920
#define O_Y1s  56672
#define O_D2s  61232
#define N_SET2 165776
#define SET_TAB_BASE 2048

__global__ void k_setup() {
    __shared__ float s_lf[64];
    int tid = threadIdx.x;
    if (tid < 64) s_lf[tid] = lgammaf(tid + 1.0f);
    __syncthreads();
    int idx = blockIdx.x * blockDim.x + tid;
    if (idx < 1344) {
        if (idx < 600) {
            int m = idx / 60, a = idx % 60;
            float th = -2.0f * PI_F * m * a / 60.0f;
            float sn, cs; sincosf(th, &sn, &cs);
            g_T60[idx] = make_float2(cs, sn);
        } else if (idx < 980) {
            int r = idx - 600; int ni = r / 20, x = r % 20;
            float th = 2.0f * PI_F * (ni - 9) * x / 20.0f;
            float sn, cs; sincosf(th, &sn, &cs);
            g_E20P[r] = make_float2(cs, sn);
        } else if (idx < 1200) {
            int r = idx - 980; int mi = r / 20, x = r % 20;
            float th = -2.0f * PI_F * (mi - 5) * x / 20.0f;
            float sn, cs; sincosf(th, &sn, &cs);
            g_E20M[r] = make_float2(cs, sn);
        } else if (idx < 1332) {
            int r = idx - 1200; int ni = r / 12, x = r % 12;
            float th = 2.0f * PI_F * (ni - 5) * x / 12.0f;
            float sn, cs; sincosf(th, &sn, &cs);
            g_E12P[r] = make_float2(cs, sn);
        } else {
            int k = idx - 1332;
            float s = 0.0f;
            for (int j = 0; j < 12; ++j) s += dh_w_f(6, j);
            g_w2n[k] = dh_w_f(6, k) / s;
        }
        return;
    }
    if (idx < SET_TAB_BASE) return;
    int i2 = idx - SET_TAB_BASE;
    if (i2 >= N_SET2) return;
    if (i2 < O_D1W) {
        int i = i2;
        int l = i / 600, b = (i % 600) / 10, m = i % 10;
        float beta = PI_F * (2 * b + 1) / 120.0f;
        g_wd_s2[i] = dh_w_f(30, b) * wigf(s_lf, l, m, 0, beta);
    } else if (i2 < O_D12W) {
        int i = i2 - O_D1W;
        int l = i / 3800; int r = i % 3800;
        int b = r / 190; int q = r % 190;
        int m = q / 19, ni = q % 19;
        float beta = PI_F * (2 * b + 1) / 40.0f;
        g_d1w[i] = (2 * l + 1) * wigf(s_lf, l, m, ni - 9, beta);
    } else if (i2 < O_D2W) {
        int i = i2 - O_D12W;
        int l = i / 1320; int r = i % 1320;
        int b = r / 66; int q = r % 66;
        int m = q / 11, ki = q % 11;
        float beta = PI_F * (2 * b + 1) / 40.0f;
        g_d12w[i] = dh_w_f(10, b) * wigf(s_lf, l, m, ki - 5, beta);
    } else if (i2 < O_Y1s) {
        int i = i2 - O_D2W;
        int l = i / 792; int r = i % 792;
        int b = r / 66; int q = r % 66;
        int m = q / 11, ni = q % 11;
        float beta = PI_F * (2 * b + 1) / 24.0f;
        g_d2w[i] = (2 * l + 1) * wigf(s_lf, l, m, ni - 5, beta);
    } else if (i2 < O_D2s) {
        int i = i2 - O_Y1s;
        int l = i / (24 * 19); int r = i % (24 * 19);
        int g = r / 19, mi = r % 19;
        int ib = g / 8, ja = g % 8;
        float beta = (ib + 1) * PI_F / 24.0f;
        float alpha = 2.0f * PI_F * ja / 8.0f;
        int m = mi - 9;
        float d = wigf(s_lf, l, m, 0, beta);
        float th = -(float)m * alpha;
        float sn, cs; sincosf(th, &sn, &cs);
        g_Y1[i] = make_float2(d * cs, d * sn);
    } else {
        int i = i2 - O_D2s;
        int l = i / (144 * 121); int r = i % (144 * 121);
        int g = r / 121; int q = r % 121;
        int ki = q / 11, ni = q % 11;
        int ib = g / 48, ja = (g / 6) % 8, kg = g % 6;
        float beta = (ib + 1) * PI_F / 24.0f;
        float alpha = 2.0f * PI_F * ja / 8.0f;
        float gamma = 2.0f * PI_F * kg / 6.0f;
        int m = ki - 5, n = ni - 5;
        float d = wigf(s_lf, l, m, n, beta);
        float th = -((float)m * alpha + (float)n * gamma);
        float sn, cs; sincosf(th, &sn, &cs);
        g_D2[i] = make_float2(d * cs, d * sn);
    }
}

// ---------------- merged prep: E1 (0..399), B2 (400..1839), X (1840..1967) ----------------
#define PREP_E1_N 400
#define PREP_B2_N 1440
#define PREP_X_BASE (PREP_E1_N + PREP_B2_N)
#define PREP_TOTAL (PREP_X_BASE + BATCH)

__global__ __launch_bounds__(256) void k_prep(const float* __restrict__ psi1,
                                              const float* __restrict__ psi2,
                                              const float* __restrict__ x) {
    __shared__ __align__(16) char sbuf[24576];
    int blk = blockIdx.x;
    int tid = threadIdx.x;

    if (blk < PREP_E1_N) {
        int b = blk % 20, o = blk / 20;
        float2* sPsi  = (float2*)sbuf;                 // 190
        float*  sd1w  = (float*)(sbuf + 1520);         // 1900
        float2* sE20P = (float2*)(sbuf + 9120);        // 380
        for (int t = tid; t < 190; t += 256) {
            int l = t / 19, ni = t % 19;
            float2 acc = make_float2(0.f, 0.f);
            for (int g = 0; g < 24; ++g) {
                float w = psi1[o * 24 + g];
                float2 y = g_Y1[(l * 24 + g) * 19 + ni];
                acc.x += w * y.x; acc.y += w * y.y;
            }
            sPsi[t] = acc;
        }
        for (int t = tid; t < 1900; t += 256) {
            int l = t / 190, m = (t / 19) % 10, ni = t % 19;
            sd1w[t] = g_d1w[((l * 20 + b) * 10 + m) * 19 + ni];
        }
        for (int t = tid; t < 380; t += 256) sE20P[t] = g_E20P[t];
        __syncthreads();
        for (int t = tid; t < 2000; t += 256) {
            int l = t % 10;
            int g = (t / 10) % 20;
            int m = t / 200;
            float2 acc = make_float2(0.f, 0.f);
            const float* dw = &sd1w[(l * 10 + m) * 19];
            const float2* ps = &sPsi[l * 19];
            for (int ni = 0; ni < 19; ++ni) {
                float d = dw[ni];
                float2 p = ps[ni];
                float2 e = sE20P[ni * 20 + g];
                acc.x += d * (p.x * e.x - p.y * e.y);
                acc.y += d * (p.x * e.y + p.y * e.x);
            }
            g_E1[(size_t)(o * 20 + b) * 2000 + t] = acc;
        }
    } else if (blk < PREP_X_BASE) {
        int q = blk - PREP_E1_N;
        int s = q / 40, rg = q % 40;
        int l = cBl[s], kk = cBkk[s];
        int kidx = kk - l + 5;
        float2* sD = (float2*)sbuf;                    // 1584
        float*  sP = (float*)(sbuf + 12672);           // 20*145
        for (int t = tid; t < 1584; t += 256) {
            int g = t / 11, ni = t % 11;
            sD[t] = g_D2[((l * 144 + g) * 11 + kidx) * 11 + ni];
        }
        int row0 = rg * 20;
        for (int t = tid; t < 20 * 144; t += 256) {
            int r = t / 144, g = t % 144;
            sP[r * 145 + g] = psi2[(size_t)(row0 + r) * 144 + g];
        }
        __syncthreads();
        if (tid < 220) {
            int rl = tid / 11, ni = tid % 11;
            int pr = row0 + rl;
            float2 acc = make_float2(0.f, 0.f);
            const float* pp = &sP[rl * 145];
            #pragma unroll 8
            for (int g = 0; g < 144; ++g) {
                float w = pp[g];
                float2 d = sD[g * 11 + ni];
                acc.x += w * d.x; acc.y += w * d.y;
            }
            int i = pr / 40, o = pr % 40;
            g_B2[(size_t)8800 * l * l + (size_t)(i * (2 * l + 1) + kk) * 440 + o * 11 + ni] = acc;
        }
    } else {
        int z = blk - PREP_X_BASE;
        float*  sx  = (float*)sbuf;                    // 3600
        float2* sxf = (float2*)(sbuf + 14400);         // 600
        for (int t = tid; t < 3600; t += 256)
            sx[t] = x[(size_t)z * 3600 + t];
        __syncthreads();
        for (int t = tid; t < 600; t += 256) {
            int b = t / 10, m = t % 10;
            float re = 0.f, im = 0.f;
            const float* row = &sx[b * 60];
            const float2* tw = &g_T60[m * 60];
            for (int a = 0; a < 60; ++a) {
                float v = row[a];
                re += v * tw[a].x; im += v * tw[a].y;
            }
            sxf[t] = make_float2(re, im);
        }
        __syncthreads();
        for (int t = tid; t < 100; t += 256) {
            int l = t / 10, m = t % 10;
            float2 acc = make_float2(0.f, 0.f);
            for (int b = 0; b < 60; ++b) {
                float w = g_wd_s2[(l * 60 + b) * 10 + m];
                float2 v = sxf[b * 10 + m];
                acc.x += w * v.x; acc.y += w * v.y;
            }
            g_X[z * 100 + m * 10 + l] = acc;
        }
    }
}

// ---------------- fused mid (radix-2, in-place A butterfly) — R10 version ----------------
__global__ __launch_bounds__(320) void k_mid() {
    __shared__ __align__(16) float2 sE1[2000]; // [m][g][l]
    __shared__ float2 sTw1[200];               // [m][a], x2 m>=1
    __shared__ float2 sEm[220];                // [mi][x]
    __shared__ __align__(16) float2 sX[1600];  // [zz][m*10+l]
    __shared__ float2 sA[1920];                // [zz][m2*20+g]
    int b = blockIdx.x, c = blockIdx.y;
    int tid = threadIdx.x;
    const float2* e1 = g_E1 + (size_t)(c * 20 + b) * 2000;
    for (int t = tid; t < 2000; t += 320) sE1[t] = e1[t];
    for (int t = tid; t < 200; t += 320) {
        int m = t / 20;
        float2 e = g_E20P[(m + 9) * 20 + t % 20];
        float s = (m >= 1) ? 2.f : 1.f;
        sTw1[t] = make_float2(s * e.x, s * e.y);
    }
    for (int t = tid; t < 220; t += 320) sEm[t] = g_E20M[t];
    __syncthreads();
    int zz = tid / 20, g = tid % 20;
    for (int stage = 0; stage < 8; ++stage) {
        int z0 = stage * 16;
        for (int t = tid; t < 1600; t += 320)
            sX[t] = g_X[(z0 + t / 100) * 100 + t % 100];
        __syncthreads();
        float2 S1m[10];
        #pragma unroll
        for (int m = 0; m < 10; ++m) {
            const float4* xp = (const float4*)&sX[zz * 100 + m * 10];
            const float4* ep = (const float4*)&sE1[(m * 20 + g) * 10];
            float ar = 0.f, ai = 0.f;
            #pragma unroll
            for (int i = 0; i < 5; ++i) {
                float4 xv = xp[i];
                float4 ev = ep[i];
                ar += xv.x * ev.x - xv.y * ev.y;
                ai += xv.x * ev.y + xv.y * ev.x;
                ar += xv.z * ev.z - xv.w * ev.w;
                ai += xv.z * ev.w + xv.w * ev.z;
            }
            S1m[m] = make_float2(ar, ai);
        }
        float ys[10], yd[10];
        #pragma unroll
        for (int a = 0; a < 10; ++a) {
            float ve = S1m[0].x, vo = 0.f;
            #pragma unroll
            for (int m = 1; m < 10; ++m) {
                float2 e = sTw1[m * 20 + a];
                float tt = S1m[m].x * e.x - S1m[m].y * e.y;
                if (m & 1) vo += tt; else ve += tt;
            }
            float y0 = fmaxf(ve + vo, 0.f);
            float y1 = fmaxf(ve - vo, 0.f);
            ys[a] = y0 + y1;
            yd[a] = y0 - y1;
        }
        #pragma unroll
        for (int m2 = 0; m2 < 6; ++m2) {
            const float2* ep = &sEm[(m2 + 5) * 20];
            const float* yy = (m2 & 1) ? yd : ys;
            float ar = 0.f, ai = 0.f;
            #pragma unroll
            for (int a = 0; a < 10; ++a) {
                ar += yy[a] * ep[a].x;
                ai += yy[a] * ep[a].y;
            }
            sA[zz * 120 + m2 * 20 + g] = make_float2(ar, ai);
        }
        __syncthreads();
        for (int t = tid; t < 960; t += 320) {
            int zz2 = t / 60, m2 = (t / 10) % 6, a = t % 10;
            int base = zz2 * 120 + m2 * 20;
            float2 p = sA[base + a];
            float2 q = sA[base + a + 10];
            sA[base + a]      = make_float2(p.x + q.x, p.y + q.y);
            sA[base + a + 10] = make_float2(p.x - q.x, p.y - q.y);
        }
        __syncthreads();
        for (int t = tid; t < 1056; t += 320) {
            int zz2 = t / 66, r = t % 66;
            int m = r / 11, ni = r % 11;
            int odd = (ni - 5) & 1;
            const float2* ap = &sA[zz2 * 120 + m * 20 + odd * 10];
            const float2* ep = &sEm[ni * 20];
            float2 acc = make_float2(0.f, 0.f);
            #pragma unroll
            for (int gg = 0; gg < 10; ++gg) {
                float2 av = ap[gg], e = ep[gg];
                acc.x += av.x * e.x - av.y * e.y;
                acc.y += av.x * e.y + av.y * e.x;
            }
            int z = z0 + zz2;
            g_Yg[((size_t)((z * 20 + c) * 20 + b)) * 66 + r] = acc;
        }
        __syncthreads();
    }
}

// ---------------- Fx packed: 2 zi per block, d12w reuse, float4 Yg loads ----------------
__global__ __launch_bounds__(256) void k_Fx() {
    __shared__ __align__(16) float2 sYs[2 * 1320]; // [pair][b][m*11+ni]
    int zi0 = blockIdx.x * 2;
    const float4* src = (const float4*)(g_Yg + (size_t)zi0 * 1320);
    float4* dst = (float4*)sYs;
    for (int t = threadIdx.x; t < 1320; t += 256)
        dst[t] = src[t];
    __syncthreads();
    int t = threadIdx.x;
    if (t < 161) {
        int p = cT2P[t];
        int kk = cT2KK[t];
        int l = cPl[p], m = cPm[p];
        int kidx = kk - l + 5;
        int off = m * 11 + kidx;
        float2 acc0 = make_float2(0.f, 0.f);
        float2 acc1 = make_float2(0.f, 0.f);
        const float* dwp = &g_d12w[(l * 20 * 6 + m) * 11 + kidx];
        const float2* y0 = &sYs[off];
        const float2* y1 = &sYs[1320 + off];
        #pragma unroll
        for (int b = 0; b < 20; ++b) {
            float d = dwp[b * 66];
            float2 v0 = y0[b * 66];
            float2 v1 = y1[b * 66];
            acc0.x += d * v0.x; acc0.y += d * v0.y;
            acc1.x += d * v1.x; acc1.y += d * v1.y;
        }
        int Kl = 20 * (2 * l + 1);
        int z = zi0 / 20, i = zi0 % 20;
        int z1 = (zi0 + 1) / 20, i1 = (zi0 + 1) % 20;
        g_Fx[(size_t)cPref[p] * 128 + (size_t)z * Kl + i * (2 * l + 1) + kk] = acc0;
        g_Fx[(size_t)cPref[p] * 128 + (size_t)z1 * Kl + i1 * (2 * l + 1) + kk] = acc1;
    }
}

// ---------------- Fo GEMM (heavy-l first, ik-paired float4, FO_ZT=4) ----------------
#define FO_ZT 4
__global__ void k_Fo() {
    __shared__ __align__(16) float2 sAa[FO_ZT * 220];
    int p = 20 - blockIdx.x;
    int z0 = blockIdx.y * FO_ZT;
    int l = cPl[p];
    int Kl = 20 * (2 * l + 1);
    size_t abase = (size_t)cPref[p] * 128 + (size_t)z0 * Kl;
    for (int t = threadIdx.x; t < FO_ZT * Kl; t += blockDim.x)
        sAa[t] = g_Fx[abase + t];
    __syncthreads();
    int t = threadIdx.x;
    if (t < 220) {
        float2 a0[FO_ZT], a1[FO_ZT];
        #pragma unroll
        for (int zz = 0; zz < FO_ZT; ++zz) { a0[zz] = make_float2(0.f, 0.f); a1[zz] = make_float2(0.f, 0.f); }
        const float4* Bp = (const float4*)(g_B2 + (size_t)8800 * l * l);
        const float4* Ap = (const float4*)sAa;
        for (int ik = 0; ik < Kl; ik += 2) {
            float4 b0 = Bp[ik * 220 + t];
            float4 b1 = Bp[(ik + 1) * 220 + t];
            #pragma unroll
            for (int zz = 0; zz < FO_ZT; ++zz) {
                float4 av = Ap[(zz * Kl + ik) >> 1]; // (re0,im0,re1,im1)
                a0[zz].x += av.x * b0.x - av.y * b0.y;
                a0[zz].y += av.x * b0.y + av.y * b0.x;
                a1[zz].x += av.x * b0.z - av.y * b0.w;
                a1[zz].y += av.x * b0.w + av.y * b0.z;
                a0[zz].x += av.z * b1.x - av.w * b1.y;
                a0[zz].y += av.z * b1.y + av.w * b1.x;
                a1[zz].x += av.z * b1.z - av.w * b1.w;
                a1[zz].y += av.z * b1.w + av.w * b1.z;
            }
        }
        int o0 = (2 * t) / 11, n0 = (2 * t) % 11;
        int o1 = (2 * t + 1) / 11, n1 = (2 * t + 1) % 11;
        #pragma unroll
        for (int zz = 0; zz < FO_ZT; ++zz) {
            int z = z0 + zz;
            g_Fo[((size_t)(z * 40 + o0) * 21 + p) * 11 + n0] = a0[zz];
            g_Fo[((size_t)(z * 40 + o1) * 21 + p) * 11 + n1] = a1[zz];
        }
    }
}

// ---------------- final: 2 zo per block, 256 threads (radix-2 both 12-pt stages) ----------------
__global__ __launch_bounds__(256) void k_final() {
    __shared__ float2 sFo[462];    // [h][p*11+ni]
    __shared__ float2 sE12[132];
    __shared__ float2 sFh2[1584];  // [h][(b*6+m)*11+ni]
    __shared__ float2 sU[1728];    // [h][(b*6+m)*12+g]
    __shared__ float  sw2[12];
    __shared__ float  sred[512];
    int zo0 = blockIdx.x * 2;
    int tid = threadIdx.x;
    for (int t = tid; t < 462; t += 256) sFo[t] = g_Fo[(size_t)zo0 * 231 + t];
    for (int t = tid; t < 132; t += 256) sE12[t] = g_E12P[t];
    if (tid < 12) sw2[tid] = g_w2n[tid];
    __syncthreads();
    for (int t = tid; t < 1584; t += 256) {
        int h = t / 792;
        int r2 = t % 792;
        int b = r2 / 66, r = r2 % 66;
        int m = r / 11, ni = r % 11;
        float2 acc = make_float2(0.f, 0.f);
        for (int l = m; l < 6; ++l) {
            float d = g_d2w[((l * 12 + b) * 6 + m) * 11 + ni];
            float2 f = sFo[h * 231 + (l * (l + 1) / 2 + m) * 11 + ni];
            acc.x += d * f.x; acc.y += d * f.y;
        }
        sFh2[t] = acc;
    }
    __syncthreads();
    for (int t = tid; t < 864; t += 256) {
        int h = t / 432;
        int r2 = t % 432;
        int bm = r2 / 6, g = r2 % 6;
        float2 ue = make_float2(0.f, 0.f), uo = make_float2(0.f, 0.f);
        const float2* fp = &sFh2[h * 792 + bm * 11];
        #pragma unroll
        for (int ni = 0; ni < 11; ++ni) {
            float2 f = fp[ni];
            float2 e = sE12[ni * 12 + g];
            float tr = f.x * e.x - f.y * e.y;
            float ti = f.x * e.y + f.y * e.x;
            if ((ni - 5) & 1) { uo.x += tr; uo.y += ti; }
            else              { ue.x += tr; ue.y += ti; }
        }
        sU[h * 864 + bm * 12 + g]     = make_float2(ue.x + uo.x, ue.y + uo.y);
        sU[h * 864 + bm * 12 + g + 6] = make_float2(ue.x - uo.x, ue.y - uo.y);
    }
    __syncthreads();
    float part0 = 0.f, part1 = 0.f;
    for (int t = tid; t < 1728; t += 256) {
        int h = t / 864;
        int r2 = t % 864;
        int bq = r2 / 72, r = r2 % 72;
        int a = r / 12, g = r % 12;
        const float2* up = &sU[h * 864 + bq * 72 + g];
        float ve = up[0].x, vo = 0.f;
        #pragma unroll
        for (int m = 1; m < 6; ++m) {
            float2 u = up[m * 12];
            float2 e = sE12[(m + 5) * 12 + a];
            float tt = 2.f * (u.x * e.x - u.y * e.y);
            if (m & 1) vo += tt; else ve += tt;
        }
        float v0 = ve + vo, v1 = ve - vo;
        float s = 0.f;
        if (v0 > 0.f) s += v0;
        if (v1 > 0.f) s += v1;
        if (h) part1 += sw2[bq] * s; else part0 += sw2[bq] * s;
    }
    sred[tid] = part0;
    sred[256 + tid] = part1;
    __syncthreads();
    for (int s = 128; s > 0; s >>= 1) {
        if (tid < s) {
            sred[tid] += sred[tid + s];
            sred[256 + tid] += sred[256 + tid + s];
        }
        __syncthreads();
    }
    if (tid == 0) {
        g_feat[zo0]     = sred[0]   * (1.0f / 144.0f);
        g_feat[zo0 + 1] = sred[256] * (1.0f / 144.0f);
    }
}

// ---------------- linear head ----------------
__global__ void k_lin(const float* __restrict__ w_lin, const float* __restrict__ b_lin,
                      float* __restrict__ out) {
    int t = blockIdx.x * blockDim.x + threadIdx.x;
    if (t >= BATCH * 10) return;
    int z = t / 10, f = t % 10;
    float acc = b_lin[f];
    #pragma unroll
    for (int o = 0; o < NF2; ++o)
        acc += g_feat[z * NF2 + o] * w_lin[f * NF2 + o];
    out[t] = acc;
}

// ---------------- launch ----------------
extern "C" void kernel_launch(void* const* d_in, const int* in_sizes, int n_in,
                              void* d_out, int out_size) {
    const float* x     = (const float*)d_in[0];
    const float* psi1  = (const float*)d_in[1];
    const float* psi2  = (const float*)d_in[2];
    const float* w_lin = (const float*)d_in[3];
    const float* b_lin = (const float*)d_in[4];
    float* out = (float*)d_out;

    k_setup<<<(SET_TAB_BASE + N_SET2 + 255) / 256, 256>>>();
    k_prep<<<PREP_TOTAL, 256>>>(psi1, psi2, x);
    k_mid<<<dim3(20, 20), 320>>>();
    k_Fx<<<BATCH * 20 / 2, 256>>>();
    k_Fo<<<dim3(21, BATCH / FO_ZT), 256>>>();
    k_final<<<BATCH * NF2 / 2, 256>>>();
    k_lin<<<(BATCH * 10 + 255) / 256, 256>>>(w_lin, b_lin, out);
}

// round 15
// speedup vs baseline: 1.0137x; 1.0009x over previous
#include <cuda_runtime.h>
#include <cuda_bf16.h>
#include <math.h>

#define PI_F 3.14159265358979323846f

#define BATCH 128
#define NF2 40

// ---------------- device tables ----------------
__device__ float  g_w2n[12];

__device__ float2 g_T60[10 * 60];        // e^{-2pi i m a/60}, m=0..9
__device__ float2 g_E20P[19 * 20];       // e^{+2pi i (ni-9) x/20}
__device__ float2 g_E20M[11 * 20];       // e^{-2pi i (mi-5) x/20}
__device__ float2 g_E12P[11 * 12];       // e^{+2pi i (ni-5) x/12}

__device__ float  g_wd_s2[10 * 60 * 10];     // [l][b][m]
__device__ float  g_d1w[10 * 20 * 10 * 19];  // [l][b][m][ni]
__device__ float  g_d12w[6 * 20 * 6 * 11];   // [l][b][m][ki]
__device__ float  g_d2w[6 * 12 * 6 * 11];    // [l][b][m][ni]
__device__ float2 g_Y1[10 * 24 * 19];        // [l][g][ni]
__device__ float2 g_D2[6 * 144 * 11 * 11];   // [l][g][ki][ni]

__device__ __align__(16) float2 g_E1[20 * 20 * 2000]; // [o][b][(m*20+g)*10+l]
__device__ __align__(16) float2 g_X[BATCH * 100];     // [z][m*10+l]
__device__ __align__(16) float2 g_Yg[(size_t)BATCH * 20 * 20 * 66]; // [z][c][b][m*11+ni]
__device__ __align__(16) float2 g_Fx[(size_t)128 * 3220]; // packed [p][z][ik]
__device__ __align__(16) float2 g_B2[316800];         // packed [l][ik][o*11+ni]
__device__ float2 g_Fo[(size_t)BATCH * NF2 * 21 * 11];// [z][o][p][ni]
__device__ float  g_feat[BATCH * NF2];

// p = (l,m) valid pairs, m<=l<=5
__constant__ int cPl[21]   = {0,1,1,2,2,2,3,3,3,3,4,4,4,4,4,5,5,5,5,5,5};
__constant__ int cPref[21] = {0,20,80,140,240,340,440,580,720,860,1000,1180,1360,1540,1720,1900,2120,2340,2560,2780,3000};
__constant__ int cOutOff[22] = {0,1,4,7,12,17,22,29,36,43,50,59,68,77,86,95,106,117,128,139,150,161};
__constant__ int cPm[21]   = {0,0,1,0,1,2,0,1,2,3,0,1,2,3,4,0,1,2,3,4,5};
__constant__ int cBl[36]  = {0,1,1,1,2,2,2,2,2,3,3,3,3,3,3,3,4,4,4,4,4,4,4,4,4,5,5,5,5,5,5,5,5,5,5,5};
__constant__ int cBkk[36] = {0,0,1,2,0,1,2,3,4,0,1,2,3,4,5,6,0,1,2,3,4,5,6,7,8,0,1,2,3,4,5,6,7,8,9,10};
// t -> (p, kk) lookup for k_Fx (t = cOutOff[p] + kk)
__constant__ signed char cT2P[161] = {
0,
1,1,1,
2,2,2,
3,3,3,3,3,
4,4,4,4,4,
5,5,5,5,5,
6,6,6,6,6,6,6,
7,7,7,7,7,7,7,
8,8,8,8,8,8,8,
9,9,9,9,9,9,9,
10,10,10,10,10,10,10,10,10,
11,11,11,11,11,11,11,11,11,
12,12,12,12,12,12,12,12,12,
13,13,13,13,13,13,13,13,13,
14,14,14,14,14,14,14,14,14,
15,15,15,15,15,15,15,15,15,15,15,
16,16,16,16,16,16,16,16,16,16,16,
17,17,17,17,17,17,17,17,17,17,17,
18,18,18,18,18,18,18,18,18,18,18,
19,19,19,19,19,19,19,19,19,19,19,
20,20,20,20,20,20,20,20,20,20,20};
__constant__ signed char cT2KK[161] = {
0,
0,1,2,
0,1,2,
0,1,2,3,4,
0,1,2,3,4,
0,1,2,3,4,
0,1,2,3,4,5,6,
0,1,2,3,4,5,6,
0,1,2,3,4,5,6,
0,1,2,3,4,5,6,
0,1,2,3,4,5,6,7,8,
0,1,2,3,4,5,6,7,8,
0,1,2,3,4,5,6,7,8,
0,1,2,3,4,5,6,7,8,
0,1,2,3,4,5,6,7,8,
0,1,2,3,4,5,6,7,8,9,10,
0,1,2,3,4,5,6,7,8,9,10,
0,1,2,3,4,5,6,7,8,9,10,
0,1,2,3,4,5,6,7,8,9,10,
0,1,2,3,4,5,6,7,8,9,10,
0,1,2,3,4,5,6,7,8,9,10};

__device__ __forceinline__ float fpow_i(float x, int p) {
    float r = 1.f;
    for (int i = 0; i < p; ++i) r *= x;
    return r;
}

__device__ float wigf(const float* lf, int l, int m, int n, float beta) {
    if (m > l || m < -l || n > l || n < -l) return 0.f;
    float cb = cosf(0.5f * beta), sb = sinf(0.5f * beta);
    float pref = 0.5f * (lf[l + m] + lf[l - m] + lf[l + n] + lf[l - n]);
    int s0 = max(0, n - m), s1 = min(l + n, l - m);
    float acc = 0.f;
    for (int s = s0; s <= s1; ++s) {
        float c = pref - (lf[l + n - s] + lf[s] + lf[m - n + s] + lf[l - m - s]);
        float t = expf(c) * fpow_i(cb, 2 * l + n - m - 2 * s) * fpow_i(sb, m - n + 2 * s);
        acc += ((m - n + s) & 1) ? -t : t;
    }
    return acc;
}

__device__ float dh_w_f(int bsz, int k) {
    float beta = PI_F * (2 * k + 1) / (4.0f * bsz);
    float s = 0.0f;
    for (int j = 0; j < bsz; ++j)
        s += sinf((2 * j + 1) * beta) / (2 * j + 1);
    return (2.0f / bsz) * sinf(beta) * s;
}

// ---------------- merged setup (all fp32) ----------------
#define O_D1W  6000
#define O_D12W 44000
#define O_D2W  51920
#define O_Y1s  56672
#define O_D2s  61232
#define N_SET2 165776
#define SET_TAB_BASE 2048

__global__ void k_setup() {
    __shared__ float s_lf[64];
    int tid = threadIdx.x;
    if (tid < 64) s_lf[tid] = lgammaf(tid + 1.0f);
    __syncthreads();
    int idx = blockIdx.x * blockDim.x + tid;
    if (idx < 1344) {
        if (idx < 600) {
            int m = idx / 60, a = idx % 60;
            float th = -2.0f * PI_F * m * a / 60.0f;
            float sn, cs; sincosf(th, &sn, &cs);
            g_T60[idx] = make_float2(cs, sn);
        } else if (idx < 980) {
            int r = idx - 600; int ni = r / 20, x = r % 20;
            float th = 2.0f * PI_F * (ni - 9) * x / 20.0f;
            float sn, cs; sincosf(th, &sn, &cs);
            g_E20P[r] = make_float2(cs, sn);
        } else if (idx < 1200) {
            int r = idx - 980; int mi = r / 20, x = r % 20;
            float th = -2.0f * PI_F * (mi - 5) * x / 20.0f;
            float sn, cs; sincosf(th, &sn, &cs);
            g_E20M[r] = make_float2(cs, sn);
        } else if (idx < 1332) {
            int r = idx - 1200; int ni = r / 12, x = r % 12;
            float th = 2.0f * PI_F * (ni - 5) * x / 12.0f;
            float sn, cs; sincosf(th, &sn, &cs);
            g_E12P[r] = make_float2(cs, sn);
        } else {
            int k = idx - 1332;
            float s = 0.0f;
            for (int j = 0; j < 12; ++j) s += dh_w_f(6, j);
            g_w2n[k] = dh_w_f(6, k) / s;
        }
        return;
    }
    if (idx < SET_TAB_BASE) return;
    int i2 = idx - SET_TAB_BASE;
    if (i2 >= N_SET2) return;
    if (i2 < O_D1W) {
        int i = i2;
        int l = i / 600, b = (i % 600) / 10, m = i % 10;
        float beta = PI_F * (2 * b + 1) / 120.0f;
        g_wd_s2[i] = dh_w_f(30, b) * wigf(s_lf, l, m, 0, beta);
    } else if (i2 < O_D12W) {
        int i = i2 - O_D1W;
        int l = i / 3800; int r = i % 3800;
        int b = r / 190; int q = r % 190;
        int m = q / 19, ni = q % 19;
        float beta = PI_F * (2 * b + 1) / 40.0f;
        g_d1w[i] = (2 * l + 1) * wigf(s_lf, l, m, ni - 9, beta);
    } else if (i2 < O_D2W) {
        int i = i2 - O_D12W;
        int l = i / 1320; int r = i % 1320;
        int b = r / 66; int q = r % 66;
        int m = q / 11, ki = q % 11;
        float beta = PI_F * (2 * b + 1) / 40.0f;
        g_d12w[i] = dh_w_f(10, b) * wigf(s_lf, l, m, ki - 5, beta);
    } else if (i2 < O_Y1s) {
        int i = i2 - O_D2W;
        int l = i / 792; int r = i % 792;
        int b = r / 66; int q = r % 66;
        int m = q / 11, ni = q % 11;
        float beta = PI_F * (2 * b + 1) / 24.0f;
        g_d2w[i] = (2 * l + 1) * wigf(s_lf, l, m, ni - 5, beta);
    } else if (i2 < O_D2s) {
        int i = i2 - O_Y1s;
        int l = i / (24 * 19); int r = i % (24 * 19);
        int g = r / 19, mi = r % 19;
        int ib = g / 8, ja = g % 8;
        float beta = (ib + 1) * PI_F / 24.0f;
        float alpha = 2.0f * PI_F * ja / 8.0f;
        int m = mi - 9;
        float d = wigf(s_lf, l, m, 0, beta);
        float th = -(float)m * alpha;
        float sn, cs; sincosf(th, &sn, &cs);
        g_Y1[i] = make_float2(d * cs, d * sn);
    } else {
        int i = i2 - O_D2s;
        int l = i / (144 * 121); int r = i % (144 * 121);
        int g = r / 121; int q = r % 121;
        int ki = q / 11, ni = q % 11;
        int ib = g / 48, ja = (g / 6) % 8, kg = g % 6;
        float beta = (ib + 1) * PI_F / 24.0f;
        float alpha = 2.0f * PI_F * ja / 8.0f;
        float gamma = 2.0f * PI_F * kg / 6.0f;
        int m = ki - 5, n = ni - 5;
        float d = wigf(s_lf, l, m, n, beta);
        float th = -((float)m * alpha + (float)n * gamma);
        float sn, cs; sincosf(th, &sn, &cs);
        g_D2[i] = make_float2(d * cs, d * sn);
    }
}

// ---------------- merged prep: E1 (0..399), B2 (400..1839), X (1840..1967) ----------------
#define PREP_E1_N 400
#define PREP_B2_N 1440
#define PREP_X_BASE (PREP_E1_N + PREP_B2_N)
#define PREP_TOTAL (PREP_X_BASE + BATCH)

__global__ __launch_bounds__(256) void k_prep(const float* __restrict__ psi1,
                                              const float* __restrict__ psi2,
                                              const float* __restrict__ x) {
    __shared__ __align__(16) char sbuf[24576];
    int blk = blockIdx.x;
    int tid = threadIdx.x;

    if (blk < PREP_E1_N) {
        int b = blk % 20, o = blk / 20;
        float2* sPsi  = (float2*)sbuf;                 // 190
        float*  sd1w  = (float*)(sbuf + 1520);         // 1900
        float2* sE20P = (float2*)(sbuf + 9120);        // 380
        for (int t = tid; t < 190; t += 256) {
            int l = t / 19, ni = t % 19;
            float2 acc = make_float2(0.f, 0.f);
            for (int g = 0; g < 24; ++g) {
                float w = psi1[o * 24 + g];
                float2 y = g_Y1[(l * 24 + g) * 19 + ni];
                acc.x += w * y.x; acc.y += w * y.y;
            }
            sPsi[t] = acc;
        }
        for (int t = tid; t < 1900; t += 256) {
            int l = t / 190, m = (t / 19) % 10, ni = t % 19;
            sd1w[t] = g_d1w[((l * 20 + b) * 10 + m) * 19 + ni];
        }
        for (int t = tid; t < 380; t += 256) sE20P[t] = g_E20P[t];
        __syncthreads();
        for (int t = tid; t < 2000; t += 256) {
            int l = t % 10;
            int g = (t / 10) % 20;
            int m = t / 200;
            float2 acc = make_float2(0.f, 0.f);
            const float* dw = &sd1w[(l * 10 + m) * 19];
            const float2* ps = &sPsi[l * 19];
            for (int ni = 0; ni < 19; ++ni) {
                float d = dw[ni];
                float2 p = ps[ni];
                float2 e = sE20P[ni * 20 + g];
                acc.x += d * (p.x * e.x - p.y * e.y);
                acc.y += d * (p.x * e.y + p.y * e.x);
            }
            g_E1[(size_t)(o * 20 + b) * 2000 + t] = acc;
        }
    } else if (blk < PREP_X_BASE) {
        int q = blk - PREP_E1_N;
        int s = q / 40, rg = q % 40;
        int l = cBl[s], kk = cBkk[s];
        int kidx = kk - l + 5;
        float2* sD = (float2*)sbuf;                    // 1584
        float*  sP = (float*)(sbuf + 12672);           // 20*145
        for (int t = tid; t < 1584; t += 256) {
            int g = t / 11, ni = t % 11;
            sD[t] = g_D2[((l * 144 + g) * 11 + kidx) * 11 + ni];
        }
        int row0 = rg * 20;
        for (int t = tid; t < 20 * 144; t += 256) {
            int r = t / 144, g = t % 144;
            sP[r * 145 + g] = psi2[(size_t)(row0 + r) * 144 + g];
        }
        __syncthreads();
        if (tid < 220) {
            int rl = tid / 11, ni = tid % 11;
            int pr = row0 + rl;
            float2 acc = make_float2(0.f, 0.f);
            const float* pp = &sP[rl * 145];
            #pragma unroll 8
            for (int g = 0; g < 144; ++g) {
                float w = pp[g];
                float2 d = sD[g * 11 + ni];
                acc.x += w * d.x; acc.y += w * d.y;
            }
            int i = pr / 40, o = pr % 40;
            g_B2[(size_t)8800 * l * l + (size_t)(i * (2 * l + 1) + kk) * 440 + o * 11 + ni] = acc;
        }
    } else {
        int z = blk - PREP_X_BASE;
        float*  sx  = (float*)sbuf;                    // 3600
        float2* sxf = (float2*)(sbuf + 14400);         // 600
        for (int t = tid; t < 3600; t += 256)
            sx[t] = x[(size_t)z * 3600 + t];
        __syncthreads();
        for (int t = tid; t < 600; t += 256) {
            int b = t / 10, m = t % 10;
            float re = 0.f, im = 0.f;
            const float* row = &sx[b * 60];
            const float2* tw = &g_T60[m * 60];
            for (int a = 0; a < 60; ++a) {
                float v = row[a];
                re += v * tw[a].x; im += v * tw[a].y;
            }
            sxf[t] = make_float2(re, im);
        }
        __syncthreads();
        for (int t = tid; t < 100; t += 256) {
            int l = t / 10, m = t % 10;
            float2 acc = make_float2(0.f, 0.f);
            for (int b = 0; b < 60; ++b) {
                float w = g_wd_s2[(l * 60 + b) * 10 + m];
                float2 v = sxf[b * 10 + m];
                acc.x += w * v.x; acc.y += w * v.y;
            }
            g_X[z * 100 + m * 10 + l] = acc;
        }
    }
}

// ---------------- fused mid (radix-2, in-place A butterfly) — R10 version ----------------
__global__ __launch_bounds__(320) void k_mid() {
    __shared__ __align__(16) float2 sE1[2000]; // [m][g][l]
    __shared__ float2 sTw1[200];               // [m][a], x2 m>=1
    __shared__ float2 sEm[220];                // [mi][x]
    __shared__ __align__(16) float2 sX[1600];  // [zz][m*10+l]
    __shared__ float2 sA[1920];                // [zz][m2*20+g]
    int b = blockIdx.x, c = blockIdx.y;
    int tid = threadIdx.x;
    const float2* e1 = g_E1 + (size_t)(c * 20 + b) * 2000;
    for (int t = tid; t < 2000; t += 320) sE1[t] = e1[t];
    for (int t = tid; t < 200; t += 320) {
        int m = t / 20;
        float2 e = g_E20P[(m + 9) * 20 + t % 20];
        float s = (m >= 1) ? 2.f : 1.f;
        sTw1[t] = make_float2(s * e.x, s * e.y);
    }
    for (int t = tid; t < 220; t += 320) sEm[t] = g_E20M[t];
    __syncthreads();
    int zz = tid / 20, g = tid % 20;
    for (int stage = 0; stage < 8; ++stage) {
        int z0 = stage * 16;
        for (int t = tid; t < 1600; t += 320)
            sX[t] = g_X[(z0 + t / 100) * 100 + t % 100];
        __syncthreads();
        float2 S1m[10];
        #pragma unroll
        for (int m = 0; m < 10; ++m) {
            const float4* xp = (const float4*)&sX[zz * 100 + m * 10];
            const float4* ep = (const float4*)&sE1[(m * 20 + g) * 10];
            float ar = 0.f, ai = 0.f;
            #pragma unroll
            for (int i = 0; i < 5; ++i) {
                float4 xv = xp[i];
                float4 ev = ep[i];
                ar += xv.x * ev.x - xv.y * ev.y;
                ai += xv.x * ev.y + xv.y * ev.x;
                ar += xv.z * ev.z - xv.w * ev.w;
                ai += xv.z * ev.w + xv.w * ev.z;
            }
            S1m[m] = make_float2(ar, ai);
        }
        float ys[10], yd[10];
        #pragma unroll
        for (int a = 0; a < 10; ++a) {
            float ve = S1m[0].x, vo = 0.f;
            #pragma unroll
            for (int m = 1; m < 10; ++m) {
                float2 e = sTw1[m * 20 + a];
                float tt = S1m[m].x * e.x - S1m[m].y * e.y;
                if (m & 1) vo += tt; else ve += tt;
            }
            float y0 = fmaxf(ve + vo, 0.f);
            float y1 = fmaxf(ve - vo, 0.f);
            ys[a] = y0 + y1;
            yd[a] = y0 - y1;
        }
        #pragma unroll
        for (int m2 = 0; m2 < 6; ++m2) {
            const float2* ep = &sEm[(m2 + 5) * 20];
            const float* yy = (m2 & 1) ? yd : ys;
            float ar = 0.f, ai = 0.f;
            #pragma unroll
            for (int a = 0; a < 10; ++a) {
                ar += yy[a] * ep[a].x;
                ai += yy[a] * ep[a].y;
            }
            sA[zz * 120 + m2 * 20 + g] = make_float2(ar, ai);
        }
        __syncthreads();
        for (int t = tid; t < 960; t += 320) {
            int zz2 = t / 60, m2 = (t / 10) % 6, a = t % 10;
            int base = zz2 * 120 + m2 * 20;
            float2 p = sA[base + a];
            float2 q = sA[base + a + 10];
            sA[base + a]      = make_float2(p.x + q.x, p.y + q.y);
            sA[base + a + 10] = make_float2(p.x - q.x, p.y - q.y);
        }
        __syncthreads();
        for (int t = tid; t < 1056; t += 320) {
            int zz2 = t / 66, r = t % 66;
            int m = r / 11, ni = r % 11;
            int odd = (ni - 5) & 1;
            const float2* ap = &sA[zz2 * 120 + m * 20 + odd * 10];
            const float2* ep = &sEm[ni * 20];
            float2 acc = make_float2(0.f, 0.f);
            #pragma unroll
            for (int gg = 0; gg < 10; ++gg) {
                float2 av = ap[gg], e = ep[gg];
                acc.x += av.x * e.x - av.y * e.y;
                acc.y += av.x * e.y + av.y * e.x;
            }
            int z = z0 + zz2;
            g_Yg[((size_t)((z * 20 + c) * 20 + b)) * 66 + r] = acc;
        }
        __syncthreads();
    }
}

// ---------------- Fx packed: 2 zi per block, 512 threads (MLP boost), float4 Yg loads ----------------
__global__ __launch_bounds__(512) void k_Fx() {
    __shared__ __align__(16) float2 sYs[2 * 1320]; // [pair][b][m*11+ni]
    int zi0 = blockIdx.x * 2;
    const float4* src = (const float4*)(g_Yg + (size_t)zi0 * 1320);
    float4* dst = (float4*)sYs;
    for (int t = threadIdx.x; t < 1320; t += 512)
        dst[t] = src[t];
    __syncthreads();
    int t = threadIdx.x;
    if (t < 161) {
        int p = cT2P[t];
        int kk = cT2KK[t];
        int l = cPl[p], m = cPm[p];
        int kidx = kk - l + 5;
        int off = m * 11 + kidx;
        float2 acc0 = make_float2(0.f, 0.f);
        float2 acc1 = make_float2(0.f, 0.f);
        const float* dwp = &g_d12w[(l * 20 * 6 + m) * 11 + kidx];
        const float2* y0 = &sYs[off];
        const float2* y1 = &sYs[1320 + off];
        #pragma unroll
        for (int b = 0; b < 20; ++b) {
            float d = dwp[b * 66];
            float2 v0 = y0[b * 66];
            float2 v1 = y1[b * 66];
            acc0.x += d * v0.x; acc0.y += d * v0.y;
            acc1.x += d * v1.x; acc1.y += d * v1.y;
        }
        int Kl = 20 * (2 * l + 1);
        int z = zi0 / 20, i = zi0 % 20;
        int z1 = (zi0 + 1) / 20, i1 = (zi0 + 1) % 20;
        g_Fx[(size_t)cPref[p] * 128 + (size_t)z * Kl + i * (2 * l + 1) + kk] = acc0;
        g_Fx[(size_t)cPref[p] * 128 + (size_t)z1 * Kl + i1 * (2 * l + 1) + kk] = acc1;
    }
}

// ---------------- Fo GEMM (heavy-l first, ik-paired float4, FO_ZT=4) ----------------
#define FO_ZT 4
__global__ void k_Fo() {
    __shared__ __align__(16) float2 sAa[FO_ZT * 220];
    int p = 20 - blockIdx.x;
    int z0 = blockIdx.y * FO_ZT;
    int l = cPl[p];
    int Kl = 20 * (2 * l + 1);
    size_t abase = (size_t)cPref[p] * 128 + (size_t)z0 * Kl;
    for (int t = threadIdx.x; t < FO_ZT * Kl; t += blockDim.x)
        sAa[t] = g_Fx[abase + t];
    __syncthreads();
    int t = threadIdx.x;
    if (t < 220) {
        float2 a0[FO_ZT], a1[FO_ZT];
        #pragma unroll
        for (int zz = 0; zz < FO_ZT; ++zz) { a0[zz] = make_float2(0.f, 0.f); a1[zz] = make_float2(0.f, 0.f); }
        const float4* Bp = (const float4*)(g_B2 + (size_t)8800 * l * l);
        const float4* Ap = (const float4*)sAa;
        for (int ik = 0; ik < Kl; ik += 2) {
            float4 b0 = Bp[ik * 220 + t];
            float4 b1 = Bp[(ik + 1) * 220 + t];
            #pragma unroll
            for (int zz = 0; zz < FO_ZT; ++zz) {
                float4 av = Ap[(zz * Kl + ik) >> 1]; // (re0,im0,re1,im1)
                a0[zz].x += av.x * b0.x - av.y * b0.y;
                a0[zz].y += av.x * b0.y + av.y * b0.x;
                a1[zz].x += av.x * b0.z - av.y * b0.w;
                a1[zz].y += av.x * b0.w + av.y * b0.z;
                a0[zz].x += av.z * b1.x - av.w * b1.y;
                a0[zz].y += av.z * b1.y + av.w * b1.x;
                a1[zz].x += av.z * b1.z - av.w * b1.w;
                a1[zz].y += av.z * b1.w + av.w * b1.z;
            }
        }
        int o0 = (2 * t) / 11, n0 = (2 * t) % 11;
        int o1 = (2 * t + 1) / 11, n1 = (2 * t + 1) % 11;
        #pragma unroll
        for (int zz = 0; zz < FO_ZT; ++zz) {
            int z = z0 + zz;
            g_Fo[((size_t)(z * 40 + o0) * 21 + p) * 11 + n0] = a0[zz];
            g_Fo[((size_t)(z * 40 + o1) * 21 + p) * 11 + n1] = a1[zz];
        }
    }
}

// ---------------- final (radix-2 on both 12-pt stages) — R12 version ----------------
__global__ void k_final() {
    __shared__ float2 sFo[231];
    __shared__ float2 sE12[132];
    __shared__ float2 sFh2[792];
    __shared__ float2 sU[864];
    __shared__ float  sw2[12];
    __shared__ float  sred[128];
    int zo = blockIdx.x;
    int tid = threadIdx.x;
    for (int t = tid; t < 231; t += 128) sFo[t] = g_Fo[(size_t)zo * 231 + t];
    for (int t = tid; t < 132; t += 128) sE12[t] = g_E12P[t];
    if (tid < 12) sw2[tid] = g_w2n[tid];
    __syncthreads();
    for (int t = tid; t < 792; t += 128) {
        int b = t / 66, r = t % 66;
        int m = r / 11, ni = r % 11;
        float2 acc = make_float2(0.f, 0.f);
        for (int l = m; l < 6; ++l) {
            float d = g_d2w[((l * 12 + b) * 6 + m) * 11 + ni];
            float2 f = sFo[(l * (l + 1) / 2 + m) * 11 + ni];
            acc.x += d * f.x; acc.y += d * f.y;
        }
        sFh2[(b * 6 + m) * 11 + ni] = acc;
    }
    __syncthreads();
    for (int t = tid; t < 432; t += 128) {
        int bm = t / 6, g = t % 6;
        float2 ue = make_float2(0.f, 0.f), uo = make_float2(0.f, 0.f);
        const float2* fp = &sFh2[bm * 11];
        #pragma unroll
        for (int ni = 0; ni < 11; ++ni) {
            float2 f = fp[ni];
            float2 e = sE12[ni * 12 + g];
            float tr = f.x * e.x - f.y * e.y;
            float ti = f.x * e.y + f.y * e.x;
            if ((ni - 5) & 1) { uo.x += tr; uo.y += ti; }
            else              { ue.x += tr; ue.y += ti; }
        }
        sU[bm * 12 + g]     = make_float2(ue.x + uo.x, ue.y + uo.y);
        sU[bm * 12 + g + 6] = make_float2(ue.x - uo.x, ue.y - uo.y);
    }
    __syncthreads();
    float part = 0.f;
    for (int t = tid; t < 864; t += 128) {
        int bq = t / 72, r = t % 72;
        int a = r / 12, g = r % 12;
        const float2* up = &sU[bq * 72 + g];
        float ve = up[0].x, vo = 0.f;
        #pragma unroll
        for (int m = 1; m < 6; ++m) {
            float2 u = up[m * 12];
            float2 e = sE12[(m + 5) * 12 + a];
            float tt = 2.f * (u.x * e.x - u.y * e.y);
            if (m & 1) vo += tt; else ve += tt;
        }
        float v0 = ve + vo, v1 = ve - vo;
        float s = 0.f;
        if (v0 > 0.f) s += v0;
        if (v1 > 0.f) s += v1;
        part += sw2[bq] * s;
    }
    sred[tid] = part;
    __syncthreads();
    for (int s = 64; s > 0; s >>= 1) {
        if (tid < s) sred[tid] += sred[tid + s];
        __syncthreads();
    }
    if (tid == 0) g_feat[zo] = sred[0] * (1.0f / 144.0f);
}

// ---------------- linear head ----------------
__global__ void k_lin(const float* __restrict__ w_lin, const float* __restrict__ b_lin,
                      float* __restrict__ out) {
    int t = blockIdx.x * blockDim.x + threadIdx.x;
    if (t >= BATCH * 10) return;
    int z = t / 10, f = t % 10;
    float acc = b_lin[f];
    #pragma unroll
    for (int o = 0; o < NF2; ++o)
        acc += g_feat[z * NF2 + o] * w_lin[f * NF2 + o];
    out[t] = acc;
}

// ---------------- launch ----------------
extern "C" void kernel_launch(void* const* d_in, const int* in_sizes, int n_in,
                              void* d_out, int out_size) {
    const float* x     = (const float*)d_in[0];
    const float* psi1  = (const float*)d_in[1];
    const float* psi2  = (const float*)d_in[2];
    const float* w_lin = (const float*)d_in[3];
    const float* b_lin = (const float*)d_in[4];
    float* out = (float*)d_out;

    k_setup<<<(SET_TAB_BASE + N_SET2 + 255) / 256, 256>>>();
    k_prep<<<PREP_TOTAL, 256>>>(psi1, psi2, x);
    k_mid<<<dim3(20, 20), 320>>>();
    k_Fx<<<BATCH * 20 / 2, 512>>>();
    k_Fo<<<dim3(21, BATCH / FO_ZT), 256>>>();
    k_final<<<BATCH * NF2, 128>>>();
    k_lin<<<(BATCH * 10 + 255) / 256, 256>>>(w_lin, b_lin, out);
}

// round 16
// speedup vs baseline: 1.0260x; 1.0121x over previous
#include <cuda_runtime.h>
#include <cuda_bf16.h>
#include <cuda_fp16.h>
#include <math.h>

#define PI_F 3.14159265358979323846f

#define BATCH 128
#define NF2 40

// ---------------- device tables ----------------
__device__ float  g_w2n[12];

__device__ float2 g_T60[10 * 60];        // e^{-2pi i m a/60}, m=0..9
__device__ float2 g_E20P[19 * 20];       // e^{+2pi i (ni-9) x/20}
__device__ float2 g_E20M[11 * 20];       // e^{-2pi i (mi-5) x/20}
__device__ float2 g_E12P[11 * 12];       // e^{+2pi i (ni-5) x/12}

__device__ float  g_wd_s2[10 * 60 * 10];     // [l][b][m]
__device__ float  g_d1w[10 * 20 * 10 * 19];  // [l][b][m][ni]
__device__ float  g_d12w[6 * 20 * 6 * 11];   // [l][b][m][ki]
__device__ float  g_d2w[6 * 12 * 6 * 11];    // [l][b][m][ni]
__device__ float2 g_Y1[10 * 24 * 19];        // [l][g][ni]
__device__ float2 g_D2[6 * 144 * 11 * 11];   // [l][g][ki][ni]

__device__ __align__(16) float2 g_E1[20 * 20 * 2000]; // [o][b][(m*20+g)*10+l]
__device__ __align__(16) float2 g_X[BATCH * 100];     // [z][m*10+l]
__device__ __align__(16) __half2 g_Yg[(size_t)BATCH * 20 * 20 * 66]; // fp16, scaled 1/64
__device__ __align__(16) float2 g_Fx[(size_t)128 * 3220]; // packed [p][z][ik]
__device__ __align__(16) float2 g_B2[316800];         // packed [l][ik][o*11+ni]
__device__ float2 g_Fo[(size_t)BATCH * NF2 * 21 * 11];// [z][o][p][ni]
__device__ float  g_feat[BATCH * NF2];

#define YG_SCALE   0.015625f
#define YG_RESCALE 64.0f

// p = (l,m) valid pairs, m<=l<=5
__constant__ int cPl[21]   = {0,1,1,2,2,2,3,3,3,3,4,4,4,4,4,5,5,5,5,5,5};
__constant__ int cPref[21] = {0,20,80,140,240,340,440,580,720,860,1000,1180,1360,1540,1720,1900,2120,2340,2560,2780,3000};
__constant__ int cOutOff[22] = {0,1,4,7,12,17,22,29,36,43,50,59,68,77,86,95,106,117,128,139,150,161};
__constant__ int cPm[21]   = {0,0,1,0,1,2,0,1,2,3,0,1,2,3,4,0,1,2,3,4,5};
__constant__ int cBl[36]  = {0,1,1,1,2,2,2,2,2,3,3,3,3,3,3,3,4,4,4,4,4,4,4,4,4,5,5,5,5,5,5,5,5,5,5,5};
__constant__ int cBkk[36] = {0,0,1,2,0,1,2,3,4,0,1,2,3,4,5,6,0,1,2,3,4,5,6,7,8,0,1,2,3,4,5,6,7,8,9,10};
// t -> (p, kk) lookup for k_Fx (t = cOutOff[p] + kk)
__constant__ signed char cT2P[161] = {
0,
1,1,1,
2,2,2,
3,3,3,3,3,
4,4,4,4,4,
5,5,5,5,5,
6,6,6,6,6,6,6,
7,7,7,7,7,7,7,
8,8,8,8,8,8,8,
9,9,9,9,9,9,9,
10,10,10,10,10,10,10,10,10,
11,11,11,11,11,11,11,11,11,
12,12,12,12,12,12,12,12,12,
13,13,13,13,13,13,13,13,13,
14,14,14,14,14,14,14,14,14,
15,15,15,15,15,15,15,15,15,15,15,
16,16,16,16,16,16,16,16,16,16,16,
17,17,17,17,17,17,17,17,17,17,17,
18,18,18,18,18,18,18,18,18,18,18,
19,19,19,19,19,19,19,19,19,19,19,
20,20,20,20,20,20,20,20,20,20,20};
__constant__ signed char cT2KK[161] = {
0,
0,1,2,
0,1,2,
0,1,2,3,4,
0,1,2,3,4,
0,1,2,3,4,
0,1,2,3,4,5,6,
0,1,2,3,4,5,6,
0,1,2,3,4,5,6,
0,1,2,3,4,5,6,
0,1,2,3,4,5,6,7,8,
0,1,2,3,4,5,6,7,8,
0,1,2,3,4,5,6,7,8,
0,1,2,3,4,5,6,7,8,
0,1,2,3,4,5,6,7,8,
0,1,2,3,4,5,6,7,8,9,10,
0,1,2,3,4,5,6,7,8,9,10,
0,1,2,3,4,5,6,7,8,9,10,
0,1,2,3,4,5,6,7,8,9,10,
0,1,2,3,4,5,6,7,8,9,10,
0,1,2,3,4,5,6,7,8,9,10};

__device__ __forceinline__ float fpow_i(float x, int p) {
    float r = 1.f;
    for (int i = 0; i < p; ++i) r *= x;
    return r;
}

__device__ float wigf(const float* lf, int l, int m, int n, float beta) {
    if (m > l || m < -l || n > l || n < -l) return 0.f;
    float cb = cosf(0.5f * beta), sb = sinf(0.5f * beta);
    float pref = 0.5f * (lf[l + m] + lf[l - m] + lf[l + n] + lf[l - n]);
    int s0 = max(0, n - m), s1 = min(l + n, l - m);
    float acc = 0.f;
    for (int s = s0; s <= s1; ++s) {
        float c = pref - (lf[l + n - s] + lf[s] + lf[m - n + s] + lf[l - m - s]);
        float t = expf(c) * fpow_i(cb, 2 * l + n - m - 2 * s) * fpow_i(sb, m - n + 2 * s);
        acc += ((m - n + s) & 1) ? -t : t;
    }
    return acc;
}

__device__ float dh_w_f(int bsz, int k) {
    float beta = PI_F * (2 * k + 1) / (4.0f * bsz);
    float s = 0.0f;
    for (int j = 0; j < bsz; ++j)
        s += sinf((2 * j + 1) * beta) / (2 * j + 1);
    return (2.0f / bsz) * sinf(beta) * s;
}

// ---------------- merged setup (all fp32) ----------------
#define O_D1W  6000
#define O_D12W 44000
#define O_D2W  51920
#define O_Y1s  56672
#define O_D2s  61232
#define N_SET2 165776
#define SET_TAB_BASE 2048

__global__ void k_setup() {
    __shared__ float s_lf[64];
    int tid = threadIdx.x;
    if (tid < 64) s_lf[tid] = lgammaf(tid + 1.0f);
    __syncthreads();
    int idx = blockIdx.x * blockDim.x + tid;
    if (idx < 1344) {
        if (idx < 600) {
            int m = idx / 60, a = idx % 60;
            float th = -2.0f * PI_F * m * a / 60.0f;
            float sn, cs; sincosf(th, &sn, &cs);
            g_T60[idx] = make_float2(cs, sn);
        } else if (idx < 980) {
            int r = idx - 600; int ni = r / 20, x = r % 20;
            float th = 2.0f * PI_F * (ni - 9) * x / 20.0f;
            float sn, cs; sincosf(th, &sn, &cs);
            g_E20P[r] = make_float2(cs, sn);
        } else if (idx < 1200) {
            int r = idx - 980; int mi = r / 20, x = r % 20;
            float th = -2.0f * PI_F * (mi - 5) * x / 20.0f;
            float sn, cs; sincosf(th, &sn, &cs);
            g_E20M[r] = make_float2(cs, sn);
        } else if (idx < 1332) {
            int r = idx - 1200; int ni = r / 12, x = r % 12;
            float th = 2.0f * PI_F * (ni - 5) * x / 12.0f;
            float sn, cs; sincosf(th, &sn, &cs);
            g_E12P[r] = make_float2(cs, sn);
        } else {
            int k = idx - 1332;
            float s = 0.0f;
            for (int j = 0; j < 12; ++j) s += dh_w_f(6, j);
            g_w2n[k] = dh_w_f(6, k) / s;
        }
        return;
    }
    if (idx < SET_TAB_BASE) return;
    int i2 = idx - SET_TAB_BASE;
    if (i2 >= N_SET2) return;
    if (i2 < O_D1W) {
        int i = i2;
        int l = i / 600, b = (i % 600) / 10, m = i % 10;
        float beta = PI_F * (2 * b + 1) / 120.0f;
        g_wd_s2[i] = dh_w_f(30, b) * wigf(s_lf, l, m, 0, beta);
    } else if (i2 < O_D12W) {
        int i = i2 - O_D1W;
        int l = i / 3800; int r = i % 3800;
        int b = r / 190; int q = r % 190;
        int m = q / 19, ni = q % 19;
        float beta = PI_F * (2 * b + 1) / 40.0f;
        g_d1w[i] = (2 * l + 1) * wigf(s_lf, l, m, ni - 9, beta);
    } else if (i2 < O_D2W) {
        int i = i2 - O_D12W;
        int l = i / 1320; int r = i % 1320;
        int b = r / 66; int q = r % 66;
        int m = q / 11, ki = q % 11;
        float beta = PI_F * (2 * b + 1) / 40.0f;
        g_d12w[i] = dh_w_f(10, b) * wigf(s_lf, l, m, ki - 5, beta);
    } else if (i2 < O_Y1s) {
        int i = i2 - O_D2W;
        int l = i / 792; int r = i % 792;
        int b = r / 66; int q = r % 66;
        int m = q / 11, ni = q % 11;
        float beta = PI_F * (2 * b + 1) / 24.0f;
        g_d2w[i] = (2 * l + 1) * wigf(s_lf, l, m, ni - 5, beta);
    } else if (i2 < O_D2s) {
        int i = i2 - O_Y1s;
        int l = i / (24 * 19); int r = i % (24 * 19);
        int g = r / 19, mi = r % 19;
        int ib = g / 8, ja = g % 8;
        float beta = (ib + 1) * PI_F / 24.0f;
        float alpha = 2.0f * PI_F * ja / 8.0f;
        int m = mi - 9;
        float d = wigf(s_lf, l, m, 0, beta);
        float th = -(float)m * alpha;
        float sn, cs; sincosf(th, &sn, &cs);
        g_Y1[i] = make_float2(d * cs, d * sn);
    } else {
        int i = i2 - O_D2s;
        int l = i / (144 * 121); int r = i % (144 * 121);
        int g = r / 121; int q = r % 121;
        int ki = q / 11, ni = q % 11;
        int ib = g / 48, ja = (g / 6) % 8, kg = g % 6;
        float beta = (ib + 1) * PI_F / 24.0f;
        float alpha = 2.0f * PI_F * ja / 8.0f;
        float gamma = 2.0f * PI_F * kg / 6.0f;
        int m = ki - 5, n = ni - 5;
        float d = wigf(s_lf, l, m, n, beta);
        float th = -((float)m * alpha + (float)n * gamma);
        float sn, cs; sincosf(th, &sn, &cs);
        g_D2[i] = make_float2(d * cs, d * sn);
    }
}

// ---------------- merged prep: E1 (0..399), B2 (400..1839), X (1840..1967) ----------------
#define PREP_E1_N 400
#define PREP_B2_N 1440
#define PREP_X_BASE (PREP_E1_N + PREP_B2_N)
#define PREP_TOTAL (PREP_X_BASE + BATCH)

__global__ __launch_bounds__(256) void k_prep(const float* __restrict__ psi1,
                                              const float* __restrict__ psi2,
                                              const float* __restrict__ x) {
    __shared__ __align__(16) char sbuf[24576];
    int blk = blockIdx.x;
    int tid = threadIdx.x;

    if (blk < PREP_E1_N) {
        int b = blk % 20, o = blk / 20;
        float2* sPsi  = (float2*)sbuf;                 // 190
        float*  sd1w  = (float*)(sbuf + 1520);         // 1900
        float2* sE20P = (float2*)(sbuf + 9120);        // 380
        for (int t = tid; t < 190; t += 256) {
            int l = t / 19, ni = t % 19;
            float2 acc = make_float2(0.f, 0.f);
            for (int g = 0; g < 24; ++g) {
                float w = psi1[o * 24 + g];
                float2 y = g_Y1[(l * 24 + g) * 19 + ni];
                acc.x += w * y.x; acc.y += w * y.y;
            }
            sPsi[t] = acc;
        }
        for (int t = tid; t < 1900; t += 256) {
            int l = t / 190, m = (t / 19) % 10, ni = t % 19;
            sd1w[t] = g_d1w[((l * 20 + b) * 10 + m) * 19 + ni];
        }
        for (int t = tid; t < 380; t += 256) sE20P[t] = g_E20P[t];
        __syncthreads();
        for (int t = tid; t < 2000; t += 256) {
            int l = t % 10;
            int g = (t / 10) % 20;
            int m = t / 200;
            float2 acc = make_float2(0.f, 0.f);
            const float* dw = &sd1w[(l * 10 + m) * 19];
            const float2* ps = &sPsi[l * 19];
            for (int ni = 0; ni < 19; ++ni) {
                float d = dw[ni];
                float2 p = ps[ni];
                float2 e = sE20P[ni * 20 + g];
                acc.x += d * (p.x * e.x - p.y * e.y);
                acc.y += d * (p.x * e.y + p.y * e.x);
            }
            g_E1[(size_t)(o * 20 + b) * 2000 + t] = acc;
        }
    } else if (blk < PREP_X_BASE) {
        int q = blk - PREP_E1_N;
        int s = q / 40, rg = q % 40;
        int l = cBl[s], kk = cBkk[s];
        int kidx = kk - l + 5;
        float2* sD = (float2*)sbuf;                    // 1584
        float*  sP = (float*)(sbuf + 12672);           // 20*145
        for (int t = tid; t < 1584; t += 256) {
            int g = t / 11, ni = t % 11;
            sD[t] = g_D2[((l * 144 + g) * 11 + kidx) * 11 + ni];
        }
        int row0 = rg * 20;
        for (int t = tid; t < 20 * 144; t += 256) {
            int r = t / 144, g = t % 144;
            sP[r * 145 + g] = psi2[(size_t)(row0 + r) * 144 + g];
        }
        __syncthreads();
        if (tid < 220) {
            int rl = tid / 11, ni = tid % 11;
            int pr = row0 + rl;
            float2 acc = make_float2(0.f, 0.f);
            const float* pp = &sP[rl * 145];
            #pragma unroll 8
            for (int g = 0; g < 144; ++g) {
                float w = pp[g];
                float2 d = sD[g * 11 + ni];
                acc.x += w * d.x; acc.y += w * d.y;
            }
            int i = pr / 40, o = pr % 40;
            g_B2[(size_t)8800 * l * l + (size_t)(i * (2 * l + 1) + kk) * 440 + o * 11 + ni] = acc;
        }
    } else {
        int z = blk - PREP_X_BASE;
        float*  sx  = (float*)sbuf;                    // 3600
        float2* sxf = (float2*)(sbuf + 14400);         // 600
        for (int t = tid; t < 3600; t += 256)
            sx[t] = x[(size_t)z * 3600 + t];
        __syncthreads();
        for (int t = tid; t < 600; t += 256) {
            int b = t / 10, m = t % 10;
            float re = 0.f, im = 0.f;
            const float* row = &sx[b * 60];
            const float2* tw = &g_T60[m * 60];
            for (int a = 0; a < 60; ++a) {
                float v = row[a];
                re += v * tw[a].x; im += v * tw[a].y;
            }
            sxf[t] = make_float2(re, im);
        }
        __syncthreads();
        for (int t = tid; t < 100; t += 256) {
            int l = t / 10, m = t % 10;
            float2 acc = make_float2(0.f, 0.f);
            for (int b = 0; b < 60; ++b) {
                float w = g_wd_s2[(l * 60 + b) * 10 + m];
                float2 v = sxf[b * 10 + m];
                acc.x += w * v.x; acc.y += w * v.y;
            }
            g_X[z * 100 + m * 10 + l] = acc;
        }
    }
}

// ---------------- fused mid (radix-2, in-place A butterfly; fp16 Yg store) ----------------
__global__ __launch_bounds__(320) void k_mid() {
    __shared__ __align__(16) float2 sE1[2000]; // [m][g][l]
    __shared__ float2 sTw1[200];               // [m][a], x2 m>=1
    __shared__ float2 sEm[220];                // [mi][x]
    __shared__ __align__(16) float2 sX[1600];  // [zz][m*10+l]
    __shared__ float2 sA[1920];                // [zz][m2*20+g]
    int b = blockIdx.x, c = blockIdx.y;
    int tid = threadIdx.x;
    const float2* e1 = g_E1 + (size_t)(c * 20 + b) * 2000;
    for (int t = tid; t < 2000; t += 320) sE1[t] = e1[t];
    for (int t = tid; t < 200; t += 320) {
        int m = t / 20;
        float2 e = g_E20P[(m + 9) * 20 + t % 20];
        float s = (m >= 1) ? 2.f : 1.f;
        sTw1[t] = make_float2(s * e.x, s * e.y);
    }
    for (int t = tid; t < 220; t += 320) sEm[t] = g_E20M[t];
    __syncthreads();
    int zz = tid / 20, g = tid % 20;
    for (int stage = 0; stage < 8; ++stage) {
        int z0 = stage * 16;
        for (int t = tid; t < 1600; t += 320)
            sX[t] = g_X[(z0 + t / 100) * 100 + t % 100];
        __syncthreads();
        float2 S1m[10];
        #pragma unroll
        for (int m = 0; m < 10; ++m) {
            const float4* xp = (const float4*)&sX[zz * 100 + m * 10];
            const float4* ep = (const float4*)&sE1[(m * 20 + g) * 10];
            float ar = 0.f, ai = 0.f;
            #pragma unroll
            for (int i = 0; i < 5; ++i) {
                float4 xv = xp[i];
                float4 ev = ep[i];
                ar += xv.x * ev.x - xv.y * ev.y;
                ai += xv.x * ev.y + xv.y * ev.x;
                ar += xv.z * ev.z - xv.w * ev.w;
                ai += xv.z * ev.w + xv.w * ev.z;
            }
            S1m[m] = make_float2(ar, ai);
        }
        float ys[10], yd[10];
        #pragma unroll
        for (int a = 0; a < 10; ++a) {
            float ve = S1m[0].x, vo = 0.f;
            #pragma unroll
            for (int m = 1; m < 10; ++m) {
                float2 e = sTw1[m * 20 + a];
                float tt = S1m[m].x * e.x - S1m[m].y * e.y;
                if (m & 1) vo += tt; else ve += tt;
            }
            float y0 = fmaxf(ve + vo, 0.f);
            float y1 = fmaxf(ve - vo, 0.f);
            ys[a] = y0 + y1;
            yd[a] = y0 - y1;
        }
        #pragma unroll
        for (int m2 = 0; m2 < 6; ++m2) {
            const float2* ep = &sEm[(m2 + 5) * 20];
            const float* yy = (m2 & 1) ? yd : ys;
            float ar = 0.f, ai = 0.f;
            #pragma unroll
            for (int a = 0; a < 10; ++a) {
                ar += yy[a] * ep[a].x;
                ai += yy[a] * ep[a].y;
            }
            sA[zz * 120 + m2 * 20 + g] = make_float2(ar, ai);
        }
        __syncthreads();
        for (int t = tid; t < 960; t += 320) {
            int zz2 = t / 60, m2 = (t / 10) % 6, a = t % 10;
            int base = zz2 * 120 + m2 * 20;
            float2 p = sA[base + a];
            float2 q = sA[base + a + 10];
            sA[base + a]      = make_float2(p.x + q.x, p.y + q.y);
            sA[base + a + 10] = make_float2(p.x - q.x, p.y - q.y);
        }
        __syncthreads();
        for (int t = tid; t < 1056; t += 320) {
            int zz2 = t / 66, r = t % 66;
            int m = r / 11, ni = r % 11;
            int odd = (ni - 5) & 1;
            const float2* ap = &sA[zz2 * 120 + m * 20 + odd * 10];
            const float2* ep = &sEm[ni * 20];
            float2 acc = make_float2(0.f, 0.f);
            #pragma unroll
            for (int gg = 0; gg < 10; ++gg) {
                float2 av = ap[gg], e = ep[gg];
                acc.x += av.x * e.x - av.y * e.y;
                acc.y += av.x * e.y + av.y * e.x;
            }
            int z = z0 + zz2;
            g_Yg[((size_t)((z * 20 + c) * 20 + b)) * 66 + r] =
                __floats2half2_rn(acc.x * YG_SCALE, acc.y * YG_SCALE);
        }
        __syncthreads();
    }
}

// ---------------- Fx packed: 2 zi per block, fp16 Yg loads, 512 threads ----------------
__global__ __launch_bounds__(512) void k_Fx() {
    __shared__ __align__(16) __half2 sYs[2 * 1320]; // [pair][b][m*11+ni]
    int zi0 = blockIdx.x * 2;
    // 2640 half2 = 10560 B = 660 float4; byte base zi0*1320*4 = zi0*5280 (16B aligned)
    const float4* src = (const float4*)(g_Yg + (size_t)zi0 * 1320);
    float4* dst = (float4*)sYs;
    for (int t = threadIdx.x; t < 660; t += 512)
        dst[t] = src[t];
    __syncthreads();
    int t = threadIdx.x;
    if (t < 161) {
        int p = cT2P[t];
        int kk = cT2KK[t];
        int l = cPl[p], m = cPm[p];
        int kidx = kk - l + 5;
        int off = m * 11 + kidx;
        float2 acc0 = make_float2(0.f, 0.f);
        float2 acc1 = make_float2(0.f, 0.f);
        const float* dwp = &g_d12w[(l * 20 * 6 + m) * 11 + kidx];
        const __half2* y0 = &sYs[off];
        const __half2* y1 = &sYs[1320 + off];
        #pragma unroll
        for (int b = 0; b < 20; ++b) {
            float d = dwp[b * 66];
            float2 v0 = __half22float2(y0[b * 66]);
            float2 v1 = __half22float2(y1[b * 66]);
            acc0.x += d * v0.x; acc0.y += d * v0.y;
            acc1.x += d * v1.x; acc1.y += d * v1.y;
        }
        acc0.x *= YG_RESCALE; acc0.y *= YG_RESCALE;
        acc1.x *= YG_RESCALE; acc1.y *= YG_RESCALE;
        int Kl = 20 * (2 * l + 1);
        int z = zi0 / 20, i = zi0 % 20;
        int z1 = (zi0 + 1) / 20, i1 = (zi0 + 1) % 20;
        g_Fx[(size_t)cPref[p] * 128 + (size_t)z * Kl + i * (2 * l + 1) + kk] = acc0;
        g_Fx[(size_t)cPref[p] * 128 + (size_t)z1 * Kl + i1 * (2 * l + 1) + kk] = acc1;
    }
}

// ---------------- Fo GEMM (heavy-l first, ik-paired float4, FO_ZT=4) ----------------
#define FO_ZT 4
__global__ void k_Fo() {
    __shared__ __align__(16) float2 sAa[FO_ZT * 220];
    int p = 20 - blockIdx.x;
    int z0 = blockIdx.y * FO_ZT;
    int l = cPl[p];
    int Kl = 20 * (2 * l + 1);
    size_t abase = (size_t)cPref[p] * 128 + (size_t)z0 * Kl;
    for (int t = threadIdx.x; t < FO_ZT * Kl; t += blockDim.x)
        sAa[t] = g_Fx[abase + t];
    __syncthreads();
    int t = threadIdx.x;
    if (t < 220) {
        float2 a0[FO_ZT], a1[FO_ZT];
        #pragma unroll
        for (int zz = 0; zz < FO_ZT; ++zz) { a0[zz] = make_float2(0.f, 0.f); a1[zz] = make_float2(0.f, 0.f); }
        const float4* Bp = (const float4*)(g_B2 + (size_t)8800 * l * l);
        const float4* Ap = (const float4*)sAa;
        for (int ik = 0; ik < Kl; ik += 2) {
            float4 b0 = Bp[ik * 220 + t];
            float4 b1 = Bp[(ik + 1) * 220 + t];
            #pragma unroll
            for (int zz = 0; zz < FO_ZT; ++zz) {
                float4 av = Ap[(zz * Kl + ik) >> 1]; // (re0,im0,re1,im1)
                a0[zz].x += av.x * b0.x - av.y * b0.y;
                a0[zz].y += av.x * b0.y + av.y * b0.x;
                a1[zz].x += av.x * b0.z - av.y * b0.w;
                a1[zz].y += av.x * b0.w + av.y * b0.z;
                a0[zz].x += av.z * b1.x - av.w * b1.y;
                a0[zz].y += av.z * b1.y + av.w * b1.x;
                a1[zz].x += av.z * b1.z - av.w * b1.w;
                a1[zz].y += av.z * b1.w + av.w * b1.z;
            }
        }
        int o0 = (2 * t) / 11, n0 = (2 * t) % 11;
        int o1 = (2 * t + 1) / 11, n1 = (2 * t + 1) % 11;
        #pragma unroll
        for (int zz = 0; zz < FO_ZT; ++zz) {
            int z = z0 + zz;
            g_Fo[((size_t)(z * 40 + o0) * 21 + p) * 11 + n0] = a0[zz];
            g_Fo[((size_t)(z * 40 + o1) * 21 + p) * 11 + n1] = a1[zz];
        }
    }
}

// ---------------- final (radix-2 on both 12-pt stages) — R12 version ----------------
__global__ void k_final() {
    __shared__ float2 sFo[231];
    __shared__ float2 sE12[132];
    __shared__ float2 sFh2[792];
    __shared__ float2 sU[864];
    __shared__ float  sw2[12];
    __shared__ float  sred[128];
    int zo = blockIdx.x;
    int tid = threadIdx.x;
    for (int t = tid; t < 231; t += 128) sFo[t] = g_Fo[(size_t)zo * 231 + t];
    for (int t = tid; t < 132; t += 128) sE12[t] = g_E12P[t];
    if (tid < 12) sw2[tid] = g_w2n[tid];
    __syncthreads();
    for (int t = tid; t < 792; t += 128) {
        int b = t / 66, r = t % 66;
        int m = r / 11, ni = r % 11;
        float2 acc = make_float2(0.f, 0.f);
        for (int l = m; l < 6; ++l) {
            float d = g_d2w[((l * 12 + b) * 6 + m) * 11 + ni];
            float2 f = sFo[(l * (l + 1) / 2 + m) * 11 + ni];
            acc.x += d * f.x; acc.y += d * f.y;
        }
        sFh2[(b * 6 + m) * 11 + ni] = acc;
    }
    __syncthreads();
    for (int t = tid; t < 432; t += 128) {
        int bm = t / 6, g = t % 6;
        float2 ue = make_float2(0.f, 0.f), uo = make_float2(0.f, 0.f);
        const float2* fp = &sFh2[bm * 11];
        #pragma unroll
        for (int ni = 0; ni < 11; ++ni) {
            float2 f = fp[ni];
            float2 e = sE12[ni * 12 + g];
            float tr = f.x * e.x - f.y * e.y;
            float ti = f.x * e.y + f.y * e.x;
            if ((ni - 5) & 1) { uo.x += tr; uo.y += ti; }
            else              { ue.x += tr; ue.y += ti; }
        }
        sU[bm * 12 + g]     = make_float2(ue.x + uo.x, ue.y + uo.y);
        sU[bm * 12 + g + 6] = make_float2(ue.x - uo.x, ue.y - uo.y);
    }
    __syncthreads();
    float part = 0.f;
    for (int t = tid; t < 864; t += 128) {
        int bq = t / 72, r = t % 72;
        int a = r / 12, g = r % 12;
        const float2* up = &sU[bq * 72 + g];
        float ve = up[0].x, vo = 0.f;
        #pragma unroll
        for (int m = 1; m < 6; ++m) {
            float2 u = up[m * 12];
            float2 e = sE12[(m + 5) * 12 + a];
            float tt = 2.f * (u.x * e.x - u.y * e.y);
            if (m & 1) vo += tt; else ve += tt;
        }
        float v0 = ve + vo, v1 = ve - vo;
        float s = 0.f;
        if (v0 > 0.f) s += v0;
        if (v1 > 0.f) s += v1;
        part += sw2[bq] * s;
    }
    sred[tid] = part;
    __syncthreads();
    for (int s = 64; s > 0; s >>= 1) {
        if (tid < s) sred[tid] += sred[tid + s];
        __syncthreads();
    }
    if (tid == 0) g_feat[zo] = sred[0] * (1.0f / 144.0f);
}

// ---------------- linear head ----------------
__global__ void k_lin(const float* __restrict__ w_lin, const float* __restrict__ b_lin,
                      float* __restrict__ out) {
    int t = blockIdx.x * blockDim.x + threadIdx.x;
    if (t >= BATCH * 10) return;
    int z = t / 10, f = t % 10;
    float acc = b_lin[f];
    #pragma unroll
    for (int o = 0; o < NF2; ++o)
        acc += g_feat[z * NF2 + o] * w_lin[f * NF2 + o];
    out[t] = acc;
}

// ---------------- launch ----------------
extern "C" void kernel_launch(void* const* d_in, const int* in_sizes, int n_in,
                              void* d_out, int out_size) {
    const float* x     = (const float*)d_in[0];
    const float* psi1  = (const float*)d_in[1];
    const float* psi2  = (const float*)d_in[2];
    const float* w_lin = (const float*)d_in[3];
    const float* b_lin = (const float*)d_in[4];
    float* out = (float*)d_out;

    k_setup<<<(SET_TAB_BASE + N_SET2 + 255) / 256, 256>>>();
    k_prep<<<PREP_TOTAL, 256>>>(psi1, psi2, x);
    k_mid<<<dim3(20, 20), 320>>>();
    k_Fx<<<BATCH * 20 / 2, 512>>>();
    k_Fo<<<dim3(21, BATCH / FO_ZT), 256>>>();
    k_final<<<BATCH * NF2, 128>>>();
    k_lin<<<(BATCH * 10 + 255) / 256, 256>>>(w_lin, b_lin, out);
}

// round 17
// speedup vs baseline: 1.0328x; 1.0066x over previous
#include <cuda_runtime.h>
#include <cuda_bf16.h>
#include <cuda_fp16.h>
#include <math.h>

#define PI_F 3.14159265358979323846f

#define BATCH 128
#define NF2 40

// ---------------- device tables ----------------
__device__ float  g_w2n[12];

__device__ float2 g_T60[10 * 60];        // e^{-2pi i m a/60}, m=0..9
__device__ float2 g_E20P[19 * 20];       // e^{+2pi i (ni-9) x/20}
__device__ float2 g_E20M[11 * 20];       // e^{-2pi i (mi-5) x/20}
__device__ float2 g_E12P[11 * 12];       // e^{+2pi i (ni-5) x/12}

__device__ float  g_wd_s2[10 * 60 * 10];     // [l][b][m]
__device__ float  g_d1w[10 * 20 * 10 * 19];  // [l][b][m][ni]
__device__ float  g_d12w[6 * 20 * 6 * 11];   // [l][b][m][ki]
__device__ float  g_d2w[6 * 12 * 6 * 11];    // [l][b][m][ni]
__device__ float2 g_Y1[10 * 24 * 19];        // [l][g][ni]
__device__ float2 g_D2[6 * 144 * 11 * 11];   // [l][g][ki][ni]

__device__ __align__(16) float2 g_E1[20 * 20 * 2000]; // [o][b][(m*20+g)*10+l]
__device__ __align__(16) float2 g_X[BATCH * 100];     // [z][m*10+l]
__device__ __align__(16) __half2 g_Yg[(size_t)BATCH * 20 * 20 * 66]; // fp16, scaled 1/64
__device__ __align__(16) float2 g_Fx[(size_t)128 * 3220]; // packed [p][z][ik]
__device__ __align__(16) float2 g_B2[316800];         // packed [l][ik][o*11+ni]
__device__ __align__(16) __half2 g_Fo[(size_t)BATCH * NF2 * 21 * 11]; // fp16, scaled 1/64
__device__ float  g_feat[BATCH * NF2];

#define YG_SCALE   0.015625f
#define YG_RESCALE 64.0f
#define FO_SCALE   0.015625f
#define FO_RESCALE 64.0f

// p = (l,m) valid pairs, m<=l<=5
__constant__ int cPl[21]   = {0,1,1,2,2,2,3,3,3,3,4,4,4,4,4,5,5,5,5,5,5};
__constant__ int cPref[21] = {0,20,80,140,240,340,440,580,720,860,1000,1180,1360,1540,1720,1900,2120,2340,2560,2780,3000};
__constant__ int cOutOff[22] = {0,1,4,7,12,17,22,29,36,43,50,59,68,77,86,95,106,117,128,139,150,161};
__constant__ int cPm[21]   = {0,0,1,0,1,2,0,1,2,3,0,1,2,3,4,0,1,2,3,4,5};
__constant__ int cBl[36]  = {0,1,1,1,2,2,2,2,2,3,3,3,3,3,3,3,4,4,4,4,4,4,4,4,4,5,5,5,5,5,5,5,5,5,5,5};
__constant__ int cBkk[36] = {0,0,1,2,0,1,2,3,4,0,1,2,3,4,5,6,0,1,2,3,4,5,6,7,8,0,1,2,3,4,5,6,7,8,9,10};
// t -> (p, kk) lookup for k_Fx (t = cOutOff[p] + kk)
__constant__ signed char cT2P[161] = {
0,
1,1,1,
2,2,2,
3,3,3,3,3,
4,4,4,4,4,
5,5,5,5,5,
6,6,6,6,6,6,6,
7,7,7,7,7,7,7,
8,8,8,8,8,8,8,
9,9,9,9,9,9,9,
10,10,10,10,10,10,10,10,10,
11,11,11,11,11,11,11,11,11,
12,12,12,12,12,12,12,12,12,
13,13,13,13,13,13,13,13,13,
14,14,14,14,14,14,14,14,14,
15,15,15,15,15,15,15,15,15,15,15,
16,16,16,16,16,16,16,16,16,16,16,
17,17,17,17,17,17,17,17,17,17,17,
18,18,18,18,18,18,18,18,18,18,18,
19,19,19,19,19,19,19,19,19,19,19,
20,20,20,20,20,20,20,20,20,20,20};
__constant__ signed char cT2KK[161] = {
0,
0,1,2,
0,1,2,
0,1,2,3,4,
0,1,2,3,4,
0,1,2,3,4,
0,1,2,3,4,5,6,
0,1,2,3,4,5,6,
0,1,2,3,4,5,6,
0,1,2,3,4,5,6,
0,1,2,3,4,5,6,7,8,
0,1,2,3,4,5,6,7,8,
0,1,2,3,4,5,6,7,8,
0,1,2,3,4,5,6,7,8,
0,1,2,3,4,5,6,7,8,
0,1,2,3,4,5,6,7,8,9,10,
0,1,2,3,4,5,6,7,8,9,10,
0,1,2,3,4,5,6,7,8,9,10,
0,1,2,3,4,5,6,7,8,9,10,
0,1,2,3,4,5,6,7,8,9,10,
0,1,2,3,4,5,6,7,8,9,10};

__device__ __forceinline__ float fpow_i(float x, int p) {
    float r = 1.f;
    for (int i = 0; i < p; ++i) r *= x;
    return r;
}

__device__ float wigf(const float* lf, int l, int m, int n, float beta) {
    if (m > l || m < -l || n > l || n < -l) return 0.f;
    float cb = cosf(0.5f * beta), sb = sinf(0.5f * beta);
    float pref = 0.5f * (lf[l + m] + lf[l - m] + lf[l + n] + lf[l - n]);
    int s0 = max(0, n - m), s1 = min(l + n, l - m);
    float acc = 0.f;
    for (int s = s0; s <= s1; ++s) {
        float c = pref - (lf[l + n - s] + lf[s] + lf[m - n + s] + lf[l - m - s]);
        float t = expf(c) * fpow_i(cb, 2 * l + n - m - 2 * s) * fpow_i(sb, m - n + 2 * s);
        acc += ((m - n + s) & 1) ? -t : t;
    }
    return acc;
}

__device__ float dh_w_f(int bsz, int k) {
    float beta = PI_F * (2 * k + 1) / (4.0f * bsz);
    float s = 0.0f;
    for (int j = 0; j < bsz; ++j)
        s += sinf((2 * j + 1) * beta) / (2 * j + 1);
    return (2.0f / bsz) * sinf(beta) * s;
}

// ---------------- merged setup (all fp32) ----------------
#define O_D1W  6000
#define O_D12W 44000
#define O_D2W  51920
#define O_Y1s  56672
#define O_D2s  61232
#define N_SET2 165776
#define SET_TAB_BASE 2048

__global__ void k_setup() {
    __shared__ float s_lf[64];
    int tid = threadIdx.x;
    if (tid < 64) s_lf[tid] = lgammaf(tid + 1.0f);
    __syncthreads();
    int idx = blockIdx.x * blockDim.x + tid;
    if (idx < 1344) {
        if (idx < 600) {
            int m = idx / 60, a = idx % 60;
            float th = -2.0f * PI_F * m * a / 60.0f;
            float sn, cs; sincosf(th, &sn, &cs);
            g_T60[idx] = make_float2(cs, sn);
        } else if (idx < 980) {
            int r = idx - 600; int ni = r / 20, x = r % 20;
            float th = 2.0f * PI_F * (ni - 9) * x / 20.0f;
            float sn, cs; sincosf(th, &sn, &cs);
            g_E20P[r] = make_float2(cs, sn);
        } else if (idx < 1200) {
            int r = idx - 980; int mi = r / 20, x = r % 20;
            float th = -2.0f * PI_F * (mi - 5) * x / 20.0f;
            float sn, cs; sincosf(th, &sn, &cs);
            g_E20M[r] = make_float2(cs, sn);
        } else if (idx < 1332) {
            int r = idx - 1200; int ni = r / 12, x = r % 12;
            float th = 2.0f * PI_F * (ni - 5) * x / 12.0f;
            float sn, cs; sincosf(th, &sn, &cs);
            g_E12P[r] = make_float2(cs, sn);
        } else {
            int k = idx - 1332;
            float s = 0.0f;
            for (int j = 0; j < 12; ++j) s += dh_w_f(6, j);
            g_w2n[k] = dh_w_f(6, k) / s;
        }
        return;
    }
    if (idx < SET_TAB_BASE) return;
    int i2 = idx - SET_TAB_BASE;
    if (i2 >= N_SET2) return;
    if (i2 < O_D1W) {
        int i = i2;
        int l = i / 600, b = (i % 600) / 10, m = i % 10;
        float beta = PI_F * (2 * b + 1) / 120.0f;
        g_wd_s2[i] = dh_w_f(30, b) * wigf(s_lf, l, m, 0, beta);
    } else if (i2 < O_D12W) {
        int i = i2 - O_D1W;
        int l = i / 3800; int r = i % 3800;
        int b = r / 190; int q = r % 190;
        int m = q / 19, ni = q % 19;
        float beta = PI_F * (2 * b + 1) / 40.0f;
        g_d1w[i] = (2 * l + 1) * wigf(s_lf, l, m, ni - 9, beta);
    } else if (i2 < O_D2W) {
        int i = i2 - O_D12W;
        int l = i / 1320; int r = i % 1320;
        int b = r / 66; int q = r % 66;
        int m = q / 11, ki = q % 11;
        float beta = PI_F * (2 * b + 1) / 40.0f;
        g_d12w[i] = dh_w_f(10, b) * wigf(s_lf, l, m, ki - 5, beta);
    } else if (i2 < O_Y1s) {
        int i = i2 - O_D2W;
        int l = i / 792; int r = i % 792;
        int b = r / 66; int q = r % 66;
        int m = q / 11, ni = q % 11;
        float beta = PI_F * (2 * b + 1) / 24.0f;
        g_d2w[i] = (2 * l + 1) * wigf(s_lf, l, m, ni - 5, beta);
    } else if (i2 < O_D2s) {
        int i = i2 - O_Y1s;
        int l = i / (24 * 19); int r = i % (24 * 19);
        int g = r / 19, mi = r % 19;
        int ib = g / 8, ja = g % 8;
        float beta = (ib + 1) * PI_F / 24.0f;
        float alpha = 2.0f * PI_F * ja / 8.0f;
        int m = mi - 9;
        float d = wigf(s_lf, l, m, 0, beta);
        float th = -(float)m * alpha;
        float sn, cs; sincosf(th, &sn, &cs);
        g_Y1[i] = make_float2(d * cs, d * sn);
    } else {
        int i = i2 - O_D2s;
        int l = i / (144 * 121); int r = i % (144 * 121);
        int g = r / 121; int q = r % 121;
        int ki = q / 11, ni = q % 11;
        int ib = g / 48, ja = (g / 6) % 8, kg = g % 6;
        float beta = (ib + 1) * PI_F / 24.0f;
        float alpha = 2.0f * PI_F * ja / 8.0f;
        float gamma = 2.0f * PI_F * kg / 6.0f;
        int m = ki - 5, n = ni - 5;
        float d = wigf(s_lf, l, m, n, beta);
        float th = -((float)m * alpha + (float)n * gamma);
        float sn, cs; sincosf(th, &sn, &cs);
        g_D2[i] = make_float2(d * cs, d * sn);
    }
}

// ---------------- merged prep: E1 (0..399), B2 (400..1839), X (1840..1967) ----------------
#define PREP_E1_N 400
#define PREP_B2_N 1440
#define PREP_X_BASE (PREP_E1_N + PREP_B2_N)
#define PREP_TOTAL (PREP_X_BASE + BATCH)

__global__ __launch_bounds__(256) void k_prep(const float* __restrict__ psi1,
                                              const float* __restrict__ psi2,
                                              const float* __restrict__ x) {
    __shared__ __align__(16) char sbuf[24576];
    int blk = blockIdx.x;
    int tid = threadIdx.x;

    if (blk < PREP_E1_N) {
        int b = blk % 20, o = blk / 20;
        float2* sPsi  = (float2*)sbuf;                 // 190
        float*  sd1w  = (float*)(sbuf + 1520);         // 1900
        float2* sE20P = (float2*)(sbuf + 9120);        // 380
        for (int t = tid; t < 190; t += 256) {
            int l = t / 19, ni = t % 19;
            float2 acc = make_float2(0.f, 0.f);
            for (int g = 0; g < 24; ++g) {
                float w = psi1[o * 24 + g];
                float2 y = g_Y1[(l * 24 + g) * 19 + ni];
                acc.x += w * y.x; acc.y += w * y.y;
            }
            sPsi[t] = acc;
        }
        for (int t = tid; t < 1900; t += 256) {
            int l = t / 190, m = (t / 19) % 10, ni = t % 19;
            sd1w[t] = g_d1w[((l * 20 + b) * 10 + m) * 19 + ni];
        }
        for (int t = tid; t < 380; t += 256) sE20P[t] = g_E20P[t];
        __syncthreads();
        for (int t = tid; t < 2000; t += 256) {
            int l = t % 10;
            int g = (t / 10) % 20;
            int m = t / 200;
            float2 acc = make_float2(0.f, 0.f);
            const float* dw = &sd1w[(l * 10 + m) * 19];
            const float2* ps = &sPsi[l * 19];
            for (int ni = 0; ni < 19; ++ni) {
                float d = dw[ni];
                float2 p = ps[ni];
                float2 e = sE20P[ni * 20 + g];
                acc.x += d * (p.x * e.x - p.y * e.y);
                acc.y += d * (p.x * e.y + p.y * e.x);
            }
            g_E1[(size_t)(o * 20 + b) * 2000 + t] = acc;
        }
    } else if (blk < PREP_X_BASE) {
        int q = blk - PREP_E1_N;
        int s = q / 40, rg = q % 40;
        int l = cBl[s], kk = cBkk[s];
        int kidx = kk - l + 5;
        float2* sD = (float2*)sbuf;                    // 1584
        float*  sP = (float*)(sbuf + 12672);           // 20*145
        for (int t = tid; t < 1584; t += 256) {
            int g = t / 11, ni = t % 11;
            sD[t] = g_D2[((l * 144 + g) * 11 + kidx) * 11 + ni];
        }
        int row0 = rg * 20;
        for (int t = tid; t < 20 * 144; t += 256) {
            int r = t / 144, g = t % 144;
            sP[r * 145 + g] = psi2[(size_t)(row0 + r) * 144 + g];
        }
        __syncthreads();
        if (tid < 220) {
            int rl = tid / 11, ni = tid % 11;
            int pr = row0 + rl;
            float2 acc = make_float2(0.f, 0.f);
            const float* pp = &sP[rl * 145];
            #pragma unroll 8
            for (int g = 0; g < 144; ++g) {
                float w = pp[g];
                float2 d = sD[g * 11 + ni];
                acc.x += w * d.x; acc.y += w * d.y;
            }
            int i = pr / 40, o = pr % 40;
            g_B2[(size_t)8800 * l * l + (size_t)(i * (2 * l + 1) + kk) * 440 + o * 11 + ni] = acc;
        }
    } else {
        int z = blk - PREP_X_BASE;
        float*  sx  = (float*)sbuf;                    // 3600
        float2* sxf = (float2*)(sbuf + 14400);         // 600
        for (int t = tid; t < 3600; t += 256)
            sx[t] = x[(size_t)z * 3600 + t];
        __syncthreads();
        for (int t = tid; t < 600; t += 256) {
            int b = t / 10, m = t % 10;
            float re = 0.f, im = 0.f;
            const float* row = &sx[b * 60];
            const float2* tw = &g_T60[m * 60];
            for (int a = 0; a < 60; ++a) {
                float v = row[a];
                re += v * tw[a].x; im += v * tw[a].y;
            }
            sxf[t] = make_float2(re, im);
        }
        __syncthreads();
        for (int t = tid; t < 100; t += 256) {
            int l = t / 10, m = t % 10;
            float2 acc = make_float2(0.f, 0.f);
            for (int b = 0; b < 60; ++b) {
                float w = g_wd_s2[(l * 60 + b) * 10 + m];
                float2 v = sxf[b * 10 + m];
                acc.x += w * v.x; acc.y += w * v.y;
            }
            g_X[z * 100 + m * 10 + l] = acc;
        }
    }
}

// ---------------- fused mid (radix-2, in-place A butterfly; fp16 Yg store) ----------------
__global__ __launch_bounds__(320) void k_mid() {
    __shared__ __align__(16) float2 sE1[2000]; // [m][g][l]
    __shared__ float2 sTw1[200];               // [m][a], x2 m>=1
    __shared__ float2 sEm[220];                // [mi][x]
    __shared__ __align__(16) float2 sX[1600];  // [zz][m*10+l]
    __shared__ float2 sA[1920];                // [zz][m2*20+g]
    int b = blockIdx.x, c = blockIdx.y;
    int tid = threadIdx.x;
    const float2* e1 = g_E1 + (size_t)(c * 20 + b) * 2000;
    for (int t = tid; t < 2000; t += 320) sE1[t] = e1[t];
    for (int t = tid; t < 200; t += 320) {
        int m = t / 20;
        float2 e = g_E20P[(m + 9) * 20 + t % 20];
        float s = (m >= 1) ? 2.f : 1.f;
        sTw1[t] = make_float2(s * e.x, s * e.y);
    }
    for (int t = tid; t < 220; t += 320) sEm[t] = g_E20M[t];
    __syncthreads();
    int zz = tid / 20, g = tid % 20;
    for (int stage = 0; stage < 8; ++stage) {
        int z0 = stage * 16;
        for (int t = tid; t < 1600; t += 320)
            sX[t] = g_X[(z0 + t / 100) * 100 + t % 100];
        __syncthreads();
        float2 S1m[10];
        #pragma unroll
        for (int m = 0; m < 10; ++m) {
            const float4* xp = (const float4*)&sX[zz * 100 + m * 10];
            const float4* ep = (const float4*)&sE1[(m * 20 + g) * 10];
            float ar = 0.f, ai = 0.f;
            #pragma unroll
            for (int i = 0; i < 5; ++i) {
                float4 xv = xp[i];
                float4 ev = ep[i];
                ar += xv.x * ev.x - xv.y * ev.y;
                ai += xv.x * ev.y + xv.y * ev.x;
                ar += xv.z * ev.z - xv.w * ev.w;
                ai += xv.z * ev.w + xv.w * ev.z;
            }
            S1m[m] = make_float2(ar, ai);
        }
        float ys[10], yd[10];
        #pragma unroll
        for (int a = 0; a < 10; ++a) {
            float ve = S1m[0].x, vo = 0.f;
            #pragma unroll
            for (int m = 1; m < 10; ++m) {
                float2 e = sTw1[m * 20 + a];
                float tt = S1m[m].x * e.x - S1m[m].y * e.y;
                if (m & 1) vo += tt; else ve += tt;
            }
            float y0 = fmaxf(ve + vo, 0.f);
            float y1 = fmaxf(ve - vo, 0.f);
            ys[a] = y0 + y1;
            yd[a] = y0 - y1;
        }
        #pragma unroll
        for (int m2 = 0; m2 < 6; ++m2) {
            const float2* ep = &sEm[(m2 + 5) * 20];
            const float* yy = (m2 & 1) ? yd : ys;
            float ar = 0.f, ai = 0.f;
            #pragma unroll
            for (int a = 0; a < 10; ++a) {
                ar += yy[a] * ep[a].x;
                ai += yy[a] * ep[a].y;
            }
            sA[zz * 120 + m2 * 20 + g] = make_float2(ar, ai);
        }
        __syncthreads();
        for (int t = tid; t < 960; t += 320) {
            int zz2 = t / 60, m2 = (t / 10) % 6, a = t % 10;
            int base = zz2 * 120 + m2 * 20;
            float2 p = sA[base + a];
            float2 q = sA[base + a + 10];
            sA[base + a]      = make_float2(p.x + q.x, p.y + q.y);
            sA[base + a + 10] = make_float2(p.x - q.x, p.y - q.y);
        }
        __syncthreads();
        for (int t = tid; t < 1056; t += 320) {
            int zz2 = t / 66, r = t % 66;
            int m = r / 11, ni = r % 11;
            int odd = (ni - 5) & 1;
            const float2* ap = &sA[zz2 * 120 + m * 20 + odd * 10];
            const float2* ep = &sEm[ni * 20];
            float2 acc = make_float2(0.f, 0.f);
            #pragma unroll
            for (int gg = 0; gg < 10; ++gg) {
                float2 av = ap[gg], e = ep[gg];
                acc.x += av.x * e.x - av.y * e.y;
                acc.y += av.x * e.y + av.y * e.x;
            }
            int z = z0 + zz2;
            g_Yg[((size_t)((z * 20 + c) * 20 + b)) * 66 + r] =
                __floats2half2_rn(acc.x * YG_SCALE, acc.y * YG_SCALE);
        }
        __syncthreads();
    }
}

// ---------------- Fx packed: 2 zi per block, fp16 Yg loads, 512 threads ----------------
__global__ __launch_bounds__(512) void k_Fx() {
    __shared__ __align__(16) __half2 sYs[2 * 1320]; // [pair][b][m*11+ni]
    int zi0 = blockIdx.x * 2;
    const float4* src = (const float4*)(g_Yg + (size_t)zi0 * 1320);
    float4* dst = (float4*)sYs;
    for (int t = threadIdx.x; t < 660; t += 512)
        dst[t] = src[t];
    __syncthreads();
    int t = threadIdx.x;
    if (t < 161) {
        int p = cT2P[t];
        int kk = cT2KK[t];
        int l = cPl[p], m = cPm[p];
        int kidx = kk - l + 5;
        int off = m * 11 + kidx;
        float2 acc0 = make_float2(0.f, 0.f);
        float2 acc1 = make_float2(0.f, 0.f);
        const float* dwp = &g_d12w[(l * 20 * 6 + m) * 11 + kidx];
        const __half2* y0 = &sYs[off];
        const __half2* y1 = &sYs[1320 + off];
        #pragma unroll
        for (int b = 0; b < 20; ++b) {
            float d = dwp[b * 66];
            float2 v0 = __half22float2(y0[b * 66]);
            float2 v1 = __half22float2(y1[b * 66]);
            acc0.x += d * v0.x; acc0.y += d * v0.y;
            acc1.x += d * v1.x; acc1.y += d * v1.y;
        }
        acc0.x *= YG_RESCALE; acc0.y *= YG_RESCALE;
        acc1.x *= YG_RESCALE; acc1.y *= YG_RESCALE;
        int Kl = 20 * (2 * l + 1);
        int z = zi0 / 20, i = zi0 % 20;
        int z1 = (zi0 + 1) / 20, i1 = (zi0 + 1) % 20;
        g_Fx[(size_t)cPref[p] * 128 + (size_t)z * Kl + i * (2 * l + 1) + kk] = acc0;
        g_Fx[(size_t)cPref[p] * 128 + (size_t)z1 * Kl + i1 * (2 * l + 1) + kk] = acc1;
    }
}

// ---------------- Fo GEMM (heavy-l first, ik-paired float4, FO_ZT=4; fp16 store) ----------------
#define FO_ZT 4
__global__ void k_Fo() {
    __shared__ __align__(16) float2 sAa[FO_ZT * 220];
    int p = 20 - blockIdx.x;
    int z0 = blockIdx.y * FO_ZT;
    int l = cPl[p];
    int Kl = 20 * (2 * l + 1);
    size_t abase = (size_t)cPref[p] * 128 + (size_t)z0 * Kl;
    for (int t = threadIdx.x; t < FO_ZT * Kl; t += blockDim.x)
        sAa[t] = g_Fx[abase + t];
    __syncthreads();
    int t = threadIdx.x;
    if (t < 220) {
        float2 a0[FO_ZT], a1[FO_ZT];
        #pragma unroll
        for (int zz = 0; zz < FO_ZT; ++zz) { a0[zz] = make_float2(0.f, 0.f); a1[zz] = make_float2(0.f, 0.f); }
        const float4* Bp = (const float4*)(g_B2 + (size_t)8800 * l * l);
        const float4* Ap = (const float4*)sAa;
        for (int ik = 0; ik < Kl; ik += 2) {
            float4 b0 = Bp[ik * 220 + t];
            float4 b1 = Bp[(ik + 1) * 220 + t];
            #pragma unroll
            for (int zz = 0; zz < FO_ZT; ++zz) {
                float4 av = Ap[(zz * Kl + ik) >> 1]; // (re0,im0,re1,im1)
                a0[zz].x += av.x * b0.x - av.y * b0.y;
                a0[zz].y += av.x * b0.y + av.y * b0.x;
                a1[zz].x += av.x * b0.z - av.y * b0.w;
                a1[zz].y += av.x * b0.w + av.y * b0.z;
                a0[zz].x += av.z * b1.x - av.w * b1.y;
                a0[zz].y += av.z * b1.y + av.w * b1.x;
                a1[zz].x += av.z * b1.z - av.w * b1.w;
                a1[zz].y += av.z * b1.w + av.w * b1.z;
            }
        }
        int o0 = (2 * t) / 11, n0 = (2 * t) % 11;
        int o1 = (2 * t + 1) / 11, n1 = (2 * t + 1) % 11;
        #pragma unroll
        for (int zz = 0; zz < FO_ZT; ++zz) {
            int z = z0 + zz;
            g_Fo[((size_t)(z * 40 + o0) * 21 + p) * 11 + n0] =
                __floats2half2_rn(a0[zz].x * FO_SCALE, a0[zz].y * FO_SCALE);
            g_Fo[((size_t)(z * 40 + o1) * 21 + p) * 11 + n1] =
                __floats2half2_rn(a1[zz].x * FO_SCALE, a1[zz].y * FO_SCALE);
        }
    }
}

// ---------------- final (radix-2 on both 12-pt stages; fp16 Fo load, rescale folded) ----------------
__global__ void k_final() {
    __shared__ float2 sFo[231];
    __shared__ float2 sE12[132];
    __shared__ float2 sFh2[792];
    __shared__ float2 sU[864];
    __shared__ float  sw2[12];
    __shared__ float  sred[128];
    int zo = blockIdx.x;
    int tid = threadIdx.x;
    for (int t = tid; t < 231; t += 128)
        sFo[t] = __half22float2(g_Fo[(size_t)zo * 231 + t]);
    for (int t = tid; t < 132; t += 128) sE12[t] = g_E12P[t];
    if (tid < 12) sw2[tid] = g_w2n[tid];
    __syncthreads();
    for (int t = tid; t < 792; t += 128) {
        int b = t / 66, r = t % 66;
        int m = r / 11, ni = r % 11;
        float2 acc = make_float2(0.f, 0.f);
        for (int l = m; l < 6; ++l) {
            float d = g_d2w[((l * 12 + b) * 6 + m) * 11 + ni];
            float2 f = sFo[(l * (l + 1) / 2 + m) * 11 + ni];
            acc.x += d * f.x; acc.y += d * f.y;
        }
        sFh2[(b * 6 + m) * 11 + ni] = acc;
    }
    __syncthreads();
    for (int t = tid; t < 432; t += 128) {
        int bm = t / 6, g = t % 6;
        float2 ue = make_float2(0.f, 0.f), uo = make_float2(0.f, 0.f);
        const float2* fp = &sFh2[bm * 11];
        #pragma unroll
        for (int ni = 0; ni < 11; ++ni) {
            float2 f = fp[ni];
            float2 e = sE12[ni * 12 + g];
            float tr = f.x * e.x - f.y * e.y;
            float ti = f.x * e.y + f.y * e.x;
            if ((ni - 5) & 1) { uo.x += tr; uo.y += ti; }
            else              { ue.x += tr; ue.y += ti; }
        }
        sU[bm * 12 + g]     = make_float2(ue.x + uo.x, ue.y + uo.y);
        sU[bm * 12 + g + 6] = make_float2(ue.x - uo.x, ue.y - uo.y);
    }
    __syncthreads();
    float part = 0.f;
    for (int t = tid; t < 864; t += 128) {
        int bq = t / 72, r = t % 72;
        int a = r / 12, g = r % 12;
        const float2* up = &sU[bq * 72 + g];
        float ve = up[0].x, vo = 0.f;
        #pragma unroll
        for (int m = 1; m < 6; ++m) {
            float2 u = up[m * 12];
            float2 e = sE12[(m + 5) * 12 + a];
            float tt = 2.f * (u.x * e.x - u.y * e.y);
            if (m & 1) vo += tt; else ve += tt;
        }
        float v0 = ve + vo, v1 = ve - vo;
        float s = 0.f;
        if (v0 > 0.f) s += v0;
        if (v1 > 0.f) s += v1;
        part += sw2[bq] * s;
    }
    sred[tid] = part;
    __syncthreads();
    for (int s = 64; s > 0; s >>= 1) {
        if (tid < s) sred[tid] += sred[tid + s];
        __syncthreads();
    }
    if (tid == 0) g_feat[zo] = sred[0] * (FO_RESCALE / 144.0f);
}

// ---------------- linear head ----------------
__global__ void k_lin(const float* __restrict__ w_lin, const float* __restrict__ b_lin,
                      float* __restrict__ out) {
    int t = blockIdx.x * blockDim.x + threadIdx.x;
    if (t >= BATCH * 10) return;
    int z = t / 10, f = t % 10;
    float acc = b_lin[f];
    #pragma unroll
    for (int o = 0; o < NF2; ++o)
        acc += g_feat[z * NF2 + o] * w_lin[f * NF2 + o];
    out[t] = acc;
}

// ---------------- launch ----------------
extern "C" void kernel_launch(void* const* d_in, const int* in_sizes, int n_in,
                              void* d_out, int out_size) {
    const float* x     = (const float*)d_in[0];
    const float* psi1  = (const float*)d_in[1];
    const float* psi2  = (const float*)d_in[2];
    const float* w_lin = (const float*)d_in[3];
    const float* b_lin = (const float*)d_in[4];
    float* out = (float*)d_out;

    k_setup<<<(SET_TAB_BASE + N_SET2 + 255) / 256, 256>>>();
    k_prep<<<PREP_TOTAL, 256>>>(psi1, psi2, x);
    k_mid<<<dim3(20, 20), 320>>>();
    k_Fx<<<BATCH * 20 / 2, 512>>>();
    k_Fo<<<dim3(21, BATCH / FO_ZT), 256>>>();
    k_final<<<BATCH * NF2, 128>>>();
    k_lin<<<(BATCH * 10 + 255) / 256, 256>>>(w_lin, b_lin, out);
}